// round 11
// baseline (speedup 1.0000x reference)
#include <cuda_runtime.h>
#include <cuda_bf16.h>
#include <cstdint>
#include <cstddef>

#define BATCH   2
#define SEQ     2048
#define DMODEL  2048
#define NHEADS  16
#define HDIM    128
#define BT      (BATCH * SEQ)   // 4096

// Scratch (device globals — allocation-free per harness rules).
static __device__ float    g_v[(size_t)BATCH * NHEADS * SEQ * HDIM];
// packed bf16 hi/mid (2 bf16 per u32)
static __device__ uint32_t g_ahi [(size_t)BT * DMODEL / 2];
static __device__ uint32_t g_amid[(size_t)BT * DMODEL / 2];
static __device__ uint32_t g_bhi [(size_t)3 * DMODEL * DMODEL / 2];
static __device__ uint32_t g_bmid[(size_t)3 * DMODEL * DMODEL / 2];
static __device__ uint32_t g_whi [(size_t)DMODEL * DMODEL / 2];
static __device__ uint32_t g_wmid[(size_t)DMODEL * DMODEL / 2];
static __device__ uint32_t g_qhi [(size_t)BATCH * NHEADS * SEQ * (HDIM / 2)];
static __device__ uint32_t g_qmid[(size_t)BATCH * NHEADS * SEQ * (HDIM / 2)];
static __device__ uint32_t g_khi [(size_t)BATCH * NHEADS * SEQ * (HDIM / 2)];
static __device__ uint32_t g_kmid[(size_t)BATCH * NHEADS * SEQ * (HDIM / 2)];
static __device__ uint32_t g_vthi [(size_t)BATCH * NHEADS * HDIM * (SEQ / 2)];
static __device__ uint32_t g_vtmid[(size_t)BATCH * NHEADS * HDIM * (SEQ / 2)];

// ---------------------------------------------------------------------------
// bf16 helpers
// ---------------------------------------------------------------------------
__device__ __forceinline__ uint32_t pack_bf16(float f_lo, float f_hi) {
    uint32_t r;
    asm("cvt.rn.bf16x2.f32 %0, %1, %2;" : "=r"(r) : "f"(f_hi), "f"(f_lo));
    return r;
}
__device__ __forceinline__ float2 unpack_bf16(uint32_t u) {
    __nv_bfloat162 h = *reinterpret_cast<__nv_bfloat162*>(&u);
    return make_float2(__bfloat162float(h.x), __bfloat162float(h.y));  // x = low
}
__device__ __forceinline__ void split2(float f0, float f1, uint32_t& hi, uint32_t& mid) {
    hi = pack_bf16(f0, f1);
    float2 hf = unpack_bf16(hi);
    mid = pack_bf16(f0 - hf.x, f1 - hf.y);
}

__device__ __forceinline__ void mma_bf16(float d[4],
                                         uint32_t a0, uint32_t a1, uint32_t a2, uint32_t a3,
                                         uint32_t b0, uint32_t b1) {
    asm volatile(
        "mma.sync.aligned.m16n8k16.row.col.f32.bf16.bf16.f32 "
        "{%0,%1,%2,%3}, {%4,%5,%6,%7}, {%8,%9}, {%0,%1,%2,%3};"
        : "+f"(d[0]), "+f"(d[1]), "+f"(d[2]), "+f"(d[3])
        : "r"(a0), "r"(a1), "r"(a2), "r"(a3), "r"(b0), "r"(b1));
}

__device__ __forceinline__ void ldm_x4(uint32_t a[4], uint32_t addr) {
    asm volatile("ldmatrix.sync.aligned.m8n8.x4.shared.b16 {%0,%1,%2,%3}, [%4];"
                 : "=r"(a[0]), "=r"(a[1]), "=r"(a[2]), "=r"(a[3]) : "r"(addr));
}
__device__ __forceinline__ void ldm_x2(uint32_t& b0, uint32_t& b1, uint32_t addr) {
    asm volatile("ldmatrix.sync.aligned.m8n8.x2.shared.b16 {%0,%1}, [%2];"
                 : "=r"(b0), "=r"(b1) : "r"(addr));
}

__device__ __forceinline__ void cp_async16(void* smem_dst, const void* gmem_src) {
    uint32_t s = (uint32_t)__cvta_generic_to_shared(smem_dst);
    asm volatile("cp.async.cg.shared.global [%0], [%1], 16;" :: "r"(s), "l"(gmem_src));
}
__device__ __forceinline__ void cp_commit() { asm volatile("cp.async.commit_group;"); }
template <int N>
__device__ __forceinline__ void cp_wait() {
    asm volatile("cp.async.wait_group %0;" :: "n"(N));
}

// ---------------------------------------------------------------------------
// Split kernel: float array -> packed bf16 (hi, mid) arrays.
// ---------------------------------------------------------------------------
__global__ void split_kernel(const float* __restrict__ in,
                             uint32_t* __restrict__ hi, uint32_t* __restrict__ mid,
                             int n4)
{
    int i = blockIdx.x * blockDim.x + threadIdx.x;
    if (i >= n4) return;
    float4 v = ((const float4*)in)[i];
    uint32_t h0, m0, h1, m1;
    split2(v.x, v.y, h0, m0);
    split2(v.z, v.w, h1, m1);
    ((uint2*)hi)[i]  = make_uint2(h0, h1);
    ((uint2*)mid)[i] = make_uint2(m0, m1);
}

// ---------------------------------------------------------------------------
// NT GEMM, packed bf16 x3, ldmatrix + cp.async double buffer.
// C[M,N] = A[M,K] * B[N,K]^T. 128(M)x64(N) block, BK=64 floats (32 u32),
// 256 threads = 8 warps (4m x 2n), warp tile 32x32. 2 CTAs/SM.
// mode 0: plain fp32 store to Cp.
// mode 1: QKV epilogue — q,k: fused RoPE (heads<8) + split -> packed globals;
//         v: fp32 scatter into [B,H,T,hd].
// ---------------------------------------------------------------------------
#define GST2 36                       // padded row stride (u32)
#define SG_AHI  0                     // u32 offsets within a stage
#define SG_AMID 4608                  // 128*36
#define SG_BHI  9216
#define SG_BMID 11520                 // 9216 + 64*36
#define SG_STAGE 13824                // u32; 55296 bytes
#define GEMM_SMEM_BYTES (2 * SG_STAGE * 4)   // 110592

__global__ __launch_bounds__(256, 2)
void gemm_nt_tc_kernel(const uint32_t* __restrict__ Ahi, const uint32_t* __restrict__ Amid,
                       const uint32_t* __restrict__ Bhi, const uint32_t* __restrict__ Bmid,
                       const float* __restrict__ cosT, const float* __restrict__ sinT,
                       uint32_t* __restrict__ Qh, uint32_t* __restrict__ Qm,
                       uint32_t* __restrict__ Kh, uint32_t* __restrict__ Km,
                       float* __restrict__ Vp, float* __restrict__ Cp,
                       int M, int N, int K, int mode)
{
    extern __shared__ uint32_t gsm[];
    const uint32_t smem_base = (uint32_t)__cvta_generic_to_shared(gsm);

    const int tid  = threadIdx.x;
    const int lane = tid & 31;
    const int wid  = tid >> 5;
    const int g    = lane >> 2;
    const int c    = lane & 3;
    const int warp_m = (wid & 3) * 32;
    const int warp_n = (wid >> 2) * 32;    // 0 or 32

    const int bm = blockIdx.y * 128;
    const int bn = blockIdx.x * 64;
    const int Ku = K >> 1;

    const uint32_t* AhiB  = Ahi  + (size_t)bm * Ku;
    const uint32_t* AmidB = Amid + (size_t)bm * Ku;
    const uint32_t* BhiB  = Bhi  + (size_t)bn * Ku;
    const uint32_t* BmidB = Bmid + (size_t)bn * Ku;

    float acc[2][4][4];
#pragma unroll
    for (int mi = 0; mi < 2; mi++)
#pragma unroll
        for (int ni = 0; ni < 4; ni++)
#pragma unroll
            for (int e = 0; e < 4; e++) acc[mi][ni][e] = 0.0f;

    const int KT = K >> 6;

    auto load_stage = [&](int kt, int st) {
        char* dst = (char*)gsm + (size_t)st * (SG_STAGE * 4);
        int ko = kt << 5;
        // A: 128 rows x 8 16B-chunks (hi+mid)
#pragma unroll
        for (int l = 0; l < 4; l++) {
            int idx = tid + l * 256;       // 0..1023
            int row = idx >> 3;
            int c4  = (idx & 7) << 2;
            size_t go = (size_t)row * Ku + ko + c4;
            uint32_t so = row * (GST2 * 4) + c4 * 4;
            cp_async16(dst + SG_AHI * 4  + so, AhiB  + go);
            cp_async16(dst + SG_AMID * 4 + so, AmidB + go);
        }
        // B: 64 rows x 8 chunks (hi+mid)
#pragma unroll
        for (int l = 0; l < 2; l++) {
            int idx = tid + l * 256;       // 0..511
            int row = idx >> 3;
            int c4  = (idx & 7) << 2;
            size_t go = (size_t)row * Ku + ko + c4;
            uint32_t so = row * (GST2 * 4) + c4 * 4;
            cp_async16(dst + SG_BHI * 4  + so, BhiB  + go);
            cp_async16(dst + SG_BMID * 4 + so, BmidB + go);
        }
    };

    // ldmatrix lane offsets (bytes)
    const uint32_t a_off = (uint32_t)(warp_m + (lane & 15)) * (GST2 * 4) + ((lane >> 4) << 4);
    const uint32_t b_off = (uint32_t)(warp_n + (lane & 7)) * (GST2 * 4) + (((lane >> 3) & 1) << 4);

    load_stage(0, 0);
    cp_commit();

    for (int kt = 0; kt < KT; kt++) {
        if (kt + 1 < KT) {
            load_stage(kt + 1, (kt + 1) & 1);
            cp_commit();
            cp_wait<1>();
        } else {
            cp_wait<0>();
        }
        __syncthreads();

        const uint32_t st_base = smem_base + (uint32_t)(kt & 1) * (SG_STAGE * 4);

#pragma unroll
        for (int kk2 = 0; kk2 < 32; kk2 += 8) {
            const uint32_t kb = kk2 * 4;
            uint32_t a_h[2][4], a_m[2][4];
            ldm_x4(a_h[0], st_base + SG_AHI * 4  + a_off + kb);
            ldm_x4(a_h[1], st_base + SG_AHI * 4  + a_off + 16 * (GST2 * 4) + kb);
            ldm_x4(a_m[0], st_base + SG_AMID * 4 + a_off + kb);
            ldm_x4(a_m[1], st_base + SG_AMID * 4 + a_off + 16 * (GST2 * 4) + kb);
            uint32_t b_h[4][2], b_m[4][2];
#pragma unroll
            for (int ni = 0; ni < 4; ni++) {
                uint32_t ad = st_base + b_off + ni * 8 * (GST2 * 4) + kb;
                ldm_x2(b_h[ni][0], b_h[ni][1], ad + SG_BHI * 4);
                ldm_x2(b_m[ni][0], b_m[ni][1], ad + SG_BMID * 4);
            }
#pragma unroll
            for (int mi = 0; mi < 2; mi++)
#pragma unroll
                for (int ni = 0; ni < 4; ni++) {
                    mma_bf16(acc[mi][ni],
                             a_h[mi][0], a_h[mi][1], a_h[mi][2], a_h[mi][3],
                             b_h[ni][0], b_h[ni][1]);
                    mma_bf16(acc[mi][ni],
                             a_h[mi][0], a_h[mi][1], a_h[mi][2], a_h[mi][3],
                             b_m[ni][0], b_m[ni][1]);
                    mma_bf16(acc[mi][ni],
                             a_m[mi][0], a_m[mi][1], a_m[mi][2], a_m[mi][3],
                             b_h[ni][0], b_h[ni][1]);
                }
        }
        __syncthreads();
    }

    if (mode == 0) {
#pragma unroll
        for (int mi = 0; mi < 2; mi++)
#pragma unroll
            for (int ni = 0; ni < 4; ni++) {
                int row0 = bm + warp_m + mi * 16 + g;
                int col  = bn + warp_n + ni * 8 + 2 * c;
                *(float2*)(Cp + (size_t)row0 * N + col) =
                    make_float2(acc[mi][ni][0], acc[mi][ni][1]);
                *(float2*)(Cp + (size_t)(row0 + 8) * N + col) =
                    make_float2(acc[mi][ni][2], acc[mi][ni][3]);
            }
    } else {
#pragma unroll
        for (int mi = 0; mi < 2; mi++)
#pragma unroll
            for (int ni = 0; ni < 4; ni++) {
                int colg   = bn + warp_n + ni * 8 + 2 * c;
                int region = colg >> 11;          // 0=q,1=k,2=v
                int h      = (colg & 2047) >> 7;
                int hc     = colg & 127;
                int p      = hc >> 1;
#pragma unroll
                for (int half = 0; half < 2; half++) {
                    int ig = bm + warp_m + mi * 16 + g + half * 8;   // b*SEQ + t
                    int b  = ig >> 11;
                    int t  = ig & 2047;
                    float v0 = acc[mi][ni][2 * half];
                    float v1 = acc[mi][ni][2 * half + 1];
                    if (region < 2) {
                        float re = v0, im = v1;
                        if (h < NHEADS / 2) {
                            float c0 = cosT[t * 64 + p];
                            float s0 = sinT[t * 64 + p];
                            re = v0 * c0 - v1 * s0;
                            im = v0 * s0 + v1 * c0;
                        }
                        uint32_t hi, mid;
                        split2(re, im, hi, mid);
                        size_t idx = (((size_t)b * NHEADS + h) * SEQ + t) * 64 + p;
                        if (region == 0) { Qh[idx] = hi; Qm[idx] = mid; }
                        else             { Kh[idx] = hi; Km[idx] = mid; }
                    } else {
                        float* pv = Vp + (((size_t)b * NHEADS + h) * SEQ + t) * HDIM + hc;
                        *(float2*)pv = make_float2(v0, v1);
                    }
                }
            }
    }
}

// ---------------------------------------------------------------------------
// V transpose + split: g_v[bh][t][d] -> vt[bh][d][t/2] packed bf16 pairs.
// ---------------------------------------------------------------------------
__global__ __launch_bounds__(256)
void vt_split_kernel(const float* __restrict__ v,
                     uint32_t* __restrict__ vthi, uint32_t* __restrict__ vtmid)
{
    __shared__ float tile[64 * 129];
    const int bhh   = blockIdx.x;
    const int chunk = blockIdx.y;
    const int tid   = threadIdx.x;

    const float* vb = v + ((size_t)bhh * SEQ + chunk * 64) * HDIM;
#pragma unroll
    for (int l = 0; l < 8; l++) {
        int slot = tid + l * 256;
        int row  = slot >> 5;
        int c4   = (slot & 31) << 2;
        float4 val = *(const float4*)(vb + row * HDIM + c4);
        tile[row * 129 + c4 + 0] = val.x;
        tile[row * 129 + c4 + 1] = val.y;
        tile[row * 129 + c4 + 2] = val.z;
        tile[row * 129 + c4 + 3] = val.w;
    }
    __syncthreads();
#pragma unroll
    for (int l = 0; l < 16; l++) {
        int slot = tid + l * 256;
        int d  = slot >> 5;
        int sp = slot & 31;
        float f0 = tile[(2 * sp)     * 129 + d];
        float f1 = tile[(2 * sp + 1) * 129 + d];
        uint32_t hi, mid;
        split2(f0, f1, hi, mid);
        size_t idx = ((size_t)bhh * 128 + d) * (SEQ / 2) + chunk * 32 + sp;
        vthi[idx]  = hi;
        vtmid[idx] = mid;
    }
}

// ---------------------------------------------------------------------------
// Flash attention: packed inputs, cp.async double buffer, ldmatrix, bf16 x3.
// Per-thread redundant m/alpha tracking (no owner threads, no psum barrier);
// P stored packed bf16 hi/mid, fragment-loaded with ldmatrix in PV.
// Block: (b*h, q-tile of 64). 256 threads = 8 warps: wm=wid&3, wn=wid>>2.
// ---------------------------------------------------------------------------
#define QK2A 68
#define VT2A 36
#define PSP  36                // packed Ps row stride (u32)
#define OFF_QHI   0
#define OFF_QMID  4352
#define OFF_KST   8704         // + st*8704 ; hi +0, mid +4352
#define K_ST_SZ   8704
#define OFF_VST   26112        // + st*9216 ; hi +0, mid +4608
#define V_ST_SZ   9216
#define OFF_PSH   44544        // 64*36 = 2304
#define OFF_PSM   46848
#define OFF_PMAX  49152        // 128 floats
#define OFF_LP    49280        // 128 floats
#define ATT_SMEM_U32 49408     // 197632 bytes

__global__ __launch_bounds__(256, 1)
void attn_tc_kernel(const uint32_t* __restrict__ qhiG, const uint32_t* __restrict__ qmidG,
                    const uint32_t* __restrict__ khiG, const uint32_t* __restrict__ kmidG,
                    const uint32_t* __restrict__ vthiG, const uint32_t* __restrict__ vtmidG,
                    uint32_t* __restrict__ outHi, uint32_t* __restrict__ outMid)
{
    extern __shared__ uint32_t smu[];
    const uint32_t smem_base = (uint32_t)__cvta_generic_to_shared(smu);
    float* pmax = (float*)(smu + OFF_PMAX);
    float* l_p  = (float*)(smu + OFF_LP);

    const int tid  = threadIdx.x;
    const int lane = tid & 31;
    const int wid  = tid >> 5;
    const int g    = lane >> 2;
    const int c    = lane & 3;
    const int wm   = wid & 3;
    const int wn   = wid >> 2;

    const int bh = blockIdx.y;
    const int qt = (int)gridDim.x - 1 - (int)blockIdx.x;   // heavy tiles first
    const int h  = bh & (NHEADS - 1);
    const int b  = bh >> 4;

    const float scale = 0.08838834764831845f;   // 1/sqrt(128)
    const int row0 = wm * 16 + g;
    const int row1 = row0 + 8;

    // --- load Q tile (packed) ---
    {
        const uint32_t* qh = qhiG  + ((size_t)bh * SEQ + qt * 64) * 64;
        const uint32_t* qm = qmidG + ((size_t)bh * SEQ + qt * 64) * 64;
#pragma unroll
        for (int l = 0; l < 4; l++) {
            int slot = tid + l * 256;
            int row  = slot >> 4;
            int q4   = (slot & 15) << 2;
            *(uint4*)(smu + OFF_QHI  + row * QK2A + q4) = *(const uint4*)(qh + row * 64 + q4);
            *(uint4*)(smu + OFF_QMID + row * QK2A + q4) = *(const uint4*)(qm + row * 64 + q4);
        }
    }

    auto load_kv = [&](int j, int st) {
        const uint32_t* kh = khiG  + ((size_t)bh * SEQ + j * 64) * 64;
        const uint32_t* km = kmidG + ((size_t)bh * SEQ + j * 64) * 64;
        uint32_t* kd = smu + OFF_KST + st * K_ST_SZ;
#pragma unroll
        for (int l = 0; l < 4; l++) {
            int slot = tid + l * 256;
            int row  = slot >> 4;
            int q4   = (slot & 15) << 2;
            cp_async16(kd + row * QK2A + q4,        kh + row * 64 + q4);
            cp_async16(kd + 4352 + row * QK2A + q4, km + row * 64 + q4);
        }
        const uint32_t* vh = vthiG  + (size_t)bh * 128 * (SEQ / 2);
        const uint32_t* vm = vtmidG + (size_t)bh * 128 * (SEQ / 2);
        uint32_t* vd = smu + OFF_VST + st * V_ST_SZ;
#pragma unroll
        for (int l = 0; l < 4; l++) {
            int slot = tid + l * 256;
            int d  = slot >> 3;
            int q4 = (slot & 7) << 2;
            cp_async16(vd + d * VT2A + q4,        vh + (size_t)d * (SEQ / 2) + j * 32 + q4);
            cp_async16(vd + 4608 + d * VT2A + q4, vm + (size_t)d * (SEQ / 2) + j * 32 + q4);
        }
    };

    float o[8][4];
#pragma unroll
    for (int ni = 0; ni < 8; ni++)
#pragma unroll
        for (int e = 0; e < 4; e++) o[ni][e] = 0.0f;
    float m0r = -1e30f, m1r = -1e30f;   // redundant per-thread row maxima
    float l0r = 0.0f,   l1r = 0.0f;     // per-thread partial row sums (8 cols each)

    // ldmatrix lane offsets (bytes)
    const uint32_t qa_off = (uint32_t)(wm * 16 + (lane & 15)) * (QK2A * 4) + ((lane >> 4) << 4);
    const uint32_t kb_off = (uint32_t)(wn * 32 + (lane & 7)) * (QK2A * 4) + (((lane >> 3) & 1) << 4);
    const uint32_t vb_off = (uint32_t)(wn * 64 + (lane & 7)) * (VT2A * 4) + (((lane >> 3) & 1) << 4);
    const uint32_t pa_off = (uint32_t)(wm * 16 + (lane & 15)) * (PSP * 4) + ((lane >> 4) << 4);

    load_kv(0, 0);
    cp_commit();

    for (int j = 0; j <= qt; j++) {
        const int st = j & 1;
        if (j < qt) {
            load_kv(j + 1, st ^ 1);
            cp_commit();
            cp_wait<1>();
        } else {
            cp_wait<0>();
        }
        __syncthreads();                      // (1) tiles ready

        // --- S = Q K^T ---
        float s[4][4];
#pragma unroll
        for (int ni = 0; ni < 4; ni++)
#pragma unroll
            for (int e = 0; e < 4; e++) s[ni][e] = 0.0f;

        const uint32_t kstb = smem_base + (OFF_KST + st * K_ST_SZ) * 4;
#pragma unroll
        for (int kk2 = 0; kk2 < 64; kk2 += 8) {
            const uint32_t kb = kk2 * 4;
            uint32_t ah[4], am[4];
            ldm_x4(ah, smem_base + OFF_QHI * 4 + qa_off + kb);
            ldm_x4(am, smem_base + OFF_QMID * 4 + qa_off + kb);
#pragma unroll
            for (int ni = 0; ni < 4; ni++) {
                uint32_t ad = kstb + kb_off + ni * 8 * (QK2A * 4) + kb;
                uint32_t bh0, bh1, bm0, bm1;
                ldm_x2(bh0, bh1, ad);
                ldm_x2(bm0, bm1, ad + 4352 * 4);
                mma_bf16(s[ni], ah[0], ah[1], ah[2], ah[3], bh0, bh1);
                mma_bf16(s[ni], ah[0], ah[1], ah[2], ah[3], bm0, bm1);
                mma_bf16(s[ni], am[0], am[1], am[2], am[3], bh0, bh1);
            }
        }

        // --- scale + causal mask ---
        const bool diag = (j == qt);
#pragma unroll
        for (int ni = 0; ni < 4; ni++) {
            int colb = wn * 32 + ni * 8 + 2 * c;
#pragma unroll
            for (int e = 0; e < 4; e++) {
                int col = colb + (e & 1);
                int row = (e < 2) ? row0 : row1;
                float val = s[ni][e] * scale;
                if (diag && col > row) val = -1e30f;
                s[ni][e] = val;
            }
        }

        // --- partial row max over this warp's 32 cols ---
        float mx0 = -1e30f, mx1 = -1e30f;
#pragma unroll
        for (int ni = 0; ni < 4; ni++) {
            mx0 = fmaxf(mx0, fmaxf(s[ni][0], s[ni][1]));
            mx1 = fmaxf(mx1, fmaxf(s[ni][2], s[ni][3]));
        }
#pragma unroll
        for (int off = 1; off < 4; off <<= 1) {
            mx0 = fmaxf(mx0, __shfl_xor_sync(0xffffffffu, mx0, off));
            mx1 = fmaxf(mx1, __shfl_xor_sync(0xffffffffu, mx1, off));
        }
        if (c == 0) {
            pmax[row0 * 2 + wn] = mx0;
            pmax[row1 * 2 + wn] = mx1;
        }
        __syncthreads();                      // (2) pmax visible

        // --- per-thread redundant m update (identical across row owners) ---
        float mn0 = fmaxf(m0r, fmaxf(pmax[row0 * 2], pmax[row0 * 2 + 1]));
        float mn1 = fmaxf(m1r, fmaxf(pmax[row1 * 2], pmax[row1 * 2 + 1]));
        float a0 = __expf(m0r - mn0);
        float a1 = __expf(m1r - mn1);
        m0r = mn0; m1r = mn1;

        // --- exp, packed P store, local l partials; alpha-rescale O ---
        float rs0 = 0.0f, rs1 = 0.0f;
#pragma unroll
        for (int ni = 0; ni < 4; ni++) {
            int pair = wn * 16 + ni * 4 + c;
            float p0 = __expf(s[ni][0] - mn0);
            float p1 = __expf(s[ni][1] - mn0);
            float p2 = __expf(s[ni][2] - mn1);
            float p3 = __expf(s[ni][3] - mn1);
            rs0 += p0 + p1; rs1 += p2 + p3;
            uint32_t hi, mid;
            split2(p0, p1, hi, mid);
            smu[OFF_PSH + row0 * PSP + pair] = hi;
            smu[OFF_PSM + row0 * PSP + pair] = mid;
            split2(p2, p3, hi, mid);
            smu[OFF_PSH + row1 * PSP + pair] = hi;
            smu[OFF_PSM + row1 * PSP + pair] = mid;
        }
        l0r = l0r * a0 + rs0;
        l1r = l1r * a1 + rs1;
#pragma unroll
        for (int ni = 0; ni < 8; ni++) {
            o[ni][0] *= a0; o[ni][1] *= a0;
            o[ni][2] *= a1; o[ni][3] *= a1;
        }
        __syncthreads();                      // (3) P visible

        // --- O += P V ---
        const uint32_t vstb = smem_base + (OFF_VST + st * V_ST_SZ) * 4;
#pragma unroll
        for (int kks = 0; kks < 64; kks += 16) {
            uint32_t ph[4], pm_[4];
            ldm_x4(ph,  smem_base + OFF_PSH * 4 + pa_off + kks * 2);
            ldm_x4(pm_, smem_base + OFF_PSM * 4 + pa_off + kks * 2);
            const uint32_t kb = (kks >> 1) * 4;
#pragma unroll
            for (int ni = 0; ni < 8; ni++) {
                uint32_t ad = vstb + vb_off + ni * 8 * (VT2A * 4) + kb;
                uint32_t bh0, bh1, bm0, bm1;
                ldm_x2(bh0, bh1, ad);
                ldm_x2(bm0, bm1, ad + 4608 * 4);
                mma_bf16(o[ni], ph[0], ph[1], ph[2], ph[3], bh0, bh1);
                mma_bf16(o[ni], ph[0], ph[1], ph[2], ph[3], bm0, bm1);
                mma_bf16(o[ni], pm_[0], pm_[1], pm_[2], pm_[3], bh0, bh1);
            }
        }
        __syncthreads();                      // (4) stage/Ps reuse safe
    }

    // --- l reduction: quad shuffle then cross-warp via smem ---
#pragma unroll
    for (int off = 1; off < 4; off <<= 1) {
        l0r += __shfl_xor_sync(0xffffffffu, l0r, off);
        l1r += __shfl_xor_sync(0xffffffffu, l1r, off);
    }
    if (c == 0) {
        l_p[row0 * 2 + wn] = l0r;
        l_p[row1 * 2 + wn] = l1r;
    }
    __syncthreads();
    float il0 = 1.0f / (l_p[row0 * 2] + l_p[row0 * 2 + 1]);
    float il1 = 1.0f / (l_p[row1 * 2] + l_p[row1 * 2 + 1]);

    size_t grow0 = (size_t)b * SEQ + qt * 64 + row0;
    size_t grow1 = (size_t)b * SEQ + qt * 64 + row1;
#pragma unroll
    for (int ni = 0; ni < 8; ni++) {
        int col  = wn * 64 + ni * 8 + 2 * c;
        int pidx = h * 64 + (col >> 1);
        uint32_t hi, mid;
        split2(o[ni][0] * il0, o[ni][1] * il0, hi, mid);
        outHi [grow0 * (DMODEL / 2) + pidx] = hi;
        outMid[grow0 * (DMODEL / 2) + pidx] = mid;
        split2(o[ni][2] * il1, o[ni][3] * il1, hi, mid);
        outHi [grow1 * (DMODEL / 2) + pidx] = hi;
        outMid[grow1 * (DMODEL / 2) + pidx] = mid;
    }
}

// ---------------------------------------------------------------------------
extern "C" void kernel_launch(void* const* d_in, const int* in_sizes, int n_in,
                              void* d_out, int out_size)
{
    const float* x    = (const float*)d_in[0];   // [2,2048,2048]
    const float* Wqkv = (const float*)d_in[1];   // [6144,2048]
    const float* Wout = (const float*)d_in[2];   // [2048,2048]
    const float* cosT = (const float*)d_in[3];   // [2048,64]
    const float* sinT = (const float*)d_in[4];   // [2048,64]
    float* out = (float*)d_out;                  // [2,2048,2048]
    (void)in_sizes; (void)n_in; (void)out_size;

    float* gv;
    uint32_t *ahi, *amid, *bhi, *bmid, *whi, *wmid;
    uint32_t *qhi, *qmid, *khi, *kmid, *vthi, *vtmid;
    cudaGetSymbolAddress((void**)&gv,    g_v);
    cudaGetSymbolAddress((void**)&ahi,   g_ahi);
    cudaGetSymbolAddress((void**)&amid,  g_amid);
    cudaGetSymbolAddress((void**)&bhi,   g_bhi);
    cudaGetSymbolAddress((void**)&bmid,  g_bmid);
    cudaGetSymbolAddress((void**)&whi,   g_whi);
    cudaGetSymbolAddress((void**)&wmid,  g_wmid);
    cudaGetSymbolAddress((void**)&qhi,   g_qhi);
    cudaGetSymbolAddress((void**)&qmid,  g_qmid);
    cudaGetSymbolAddress((void**)&khi,   g_khi);
    cudaGetSymbolAddress((void**)&kmid,  g_kmid);
    cudaGetSymbolAddress((void**)&vthi,  g_vthi);
    cudaGetSymbolAddress((void**)&vtmid, g_vtmid);

    const int attn_smem = ATT_SMEM_U32 * (int)sizeof(uint32_t);   // 197632
    cudaFuncSetAttribute(gemm_nt_tc_kernel,
                         cudaFuncAttributeMaxDynamicSharedMemorySize, GEMM_SMEM_BYTES);
    cudaFuncSetAttribute(attn_tc_kernel,
                         cudaFuncAttributeMaxDynamicSharedMemorySize, attn_smem);

    // 1-3) splits (Wout into its own buffers so the order is capture-friendly)
    split_kernel<<<(BT * DMODEL / 4 + 255) / 256, 256>>>(x, ahi, amid, BT * DMODEL / 4);
    split_kernel<<<(3 * DMODEL * DMODEL / 4 + 255) / 256, 256>>>(Wqkv, bhi, bmid,
                                                                 3 * DMODEL * DMODEL / 4);
    split_kernel<<<(DMODEL * DMODEL / 4 + 255) / 256, 256>>>(Wout, whi, wmid,
                                                             DMODEL * DMODEL / 4);

    // 4) QKV projection (4th launch — ncu profiles this one)
    gemm_nt_tc_kernel<<<dim3(96, 32), 256, GEMM_SMEM_BYTES>>>(
        ahi, amid, bhi, bmid, cosT, sinT,
        qhi, qmid, khi, kmid, gv, nullptr, BT, 3 * DMODEL, DMODEL, 1);

    // 5) V transpose + split into packed Vt
    vt_split_kernel<<<dim3(BATCH * NHEADS, SEQ / 64), 256>>>(gv, vthi, vtmid);

    // 6) Causal flash attention; writes packed A operand for the out-proj
    attn_tc_kernel<<<dim3(SEQ / 64, BATCH * NHEADS), 256, attn_smem>>>(
        qhi, qmid, khi, kmid, vthi, vtmid, ahi, amid);

    // 7) Output projection into d_out
    gemm_nt_tc_kernel<<<dim3(32, 32), 256, GEMM_SMEM_BYTES>>>(
        ahi, amid, whi, wmid, nullptr, nullptr,
        nullptr, nullptr, nullptr, nullptr, nullptr, out, BT, DMODEL, DMODEL, 0);
}

// round 13
// speedup vs baseline: 1.3997x; 1.3997x over previous
#include <cuda_runtime.h>
#include <cuda_bf16.h>
#include <cstdint>
#include <cstddef>

#define BATCH   2
#define SEQ     2048
#define DMODEL  2048
#define NHEADS  16
#define HDIM    128
#define BT      (BATCH * SEQ)   // 4096

// Scratch (device globals — allocation-free per harness rules).
static __device__ float    g_v[(size_t)BATCH * NHEADS * SEQ * HDIM];
// packed bf16 hi/mid (2 bf16 per u32)
static __device__ uint32_t g_ahi [(size_t)BT * DMODEL / 2];
static __device__ uint32_t g_amid[(size_t)BT * DMODEL / 2];
static __device__ uint32_t g_bhi [(size_t)3 * DMODEL * DMODEL / 2];
static __device__ uint32_t g_bmid[(size_t)3 * DMODEL * DMODEL / 2];
static __device__ uint32_t g_whi [(size_t)DMODEL * DMODEL / 2];
static __device__ uint32_t g_wmid[(size_t)DMODEL * DMODEL / 2];
static __device__ uint32_t g_qhi [(size_t)BATCH * NHEADS * SEQ * (HDIM / 2)];
static __device__ uint32_t g_qmid[(size_t)BATCH * NHEADS * SEQ * (HDIM / 2)];
static __device__ uint32_t g_khi [(size_t)BATCH * NHEADS * SEQ * (HDIM / 2)];
static __device__ uint32_t g_kmid[(size_t)BATCH * NHEADS * SEQ * (HDIM / 2)];
static __device__ uint32_t g_vthi [(size_t)BATCH * NHEADS * HDIM * (SEQ / 2)];
static __device__ uint32_t g_vtmid[(size_t)BATCH * NHEADS * HDIM * (SEQ / 2)];

// ---------------------------------------------------------------------------
// bf16 helpers
// ---------------------------------------------------------------------------
__device__ __forceinline__ uint32_t pack_bf16(float f_lo, float f_hi) {
    uint32_t r;
    asm("cvt.rn.bf16x2.f32 %0, %1, %2;" : "=r"(r) : "f"(f_hi), "f"(f_lo));
    return r;
}
__device__ __forceinline__ float2 unpack_bf16(uint32_t u) {
    __nv_bfloat162 h = *reinterpret_cast<__nv_bfloat162*>(&u);
    return make_float2(__bfloat162float(h.x), __bfloat162float(h.y));  // x = low
}
__device__ __forceinline__ void split2(float f0, float f1, uint32_t& hi, uint32_t& mid) {
    hi = pack_bf16(f0, f1);
    float2 hf = unpack_bf16(hi);
    mid = pack_bf16(f0 - hf.x, f1 - hf.y);
}

__device__ __forceinline__ void mma_bf16(float d[4],
                                         uint32_t a0, uint32_t a1, uint32_t a2, uint32_t a3,
                                         uint32_t b0, uint32_t b1) {
    asm volatile(
        "mma.sync.aligned.m16n8k16.row.col.f32.bf16.bf16.f32 "
        "{%0,%1,%2,%3}, {%4,%5,%6,%7}, {%8,%9}, {%0,%1,%2,%3};"
        : "+f"(d[0]), "+f"(d[1]), "+f"(d[2]), "+f"(d[3])
        : "r"(a0), "r"(a1), "r"(a2), "r"(a3), "r"(b0), "r"(b1));
}

__device__ __forceinline__ void ldm_x4(uint32_t a[4], uint32_t addr) {
    asm volatile("ldmatrix.sync.aligned.m8n8.x4.shared.b16 {%0,%1,%2,%3}, [%4];"
                 : "=r"(a[0]), "=r"(a[1]), "=r"(a[2]), "=r"(a[3]) : "r"(addr));
}
__device__ __forceinline__ void ldm_x2(uint32_t& b0, uint32_t& b1, uint32_t addr) {
    asm volatile("ldmatrix.sync.aligned.m8n8.x2.shared.b16 {%0,%1}, [%2];"
                 : "=r"(b0), "=r"(b1) : "r"(addr));
}

__device__ __forceinline__ void cp_async16(void* smem_dst, const void* gmem_src) {
    uint32_t s = (uint32_t)__cvta_generic_to_shared(smem_dst);
    asm volatile("cp.async.cg.shared.global [%0], [%1], 16;" :: "r"(s), "l"(gmem_src));
}
__device__ __forceinline__ void cp_commit() { asm volatile("cp.async.commit_group;"); }
template <int N>
__device__ __forceinline__ void cp_wait() {
    asm volatile("cp.async.wait_group %0;" :: "n"(N));
}

// ---------------------------------------------------------------------------
// Split kernel: float array -> packed bf16 (hi, mid) arrays.
// ---------------------------------------------------------------------------
__global__ void split_kernel(const float* __restrict__ in,
                             uint32_t* __restrict__ hi, uint32_t* __restrict__ mid,
                             int n4)
{
    int i = blockIdx.x * blockDim.x + threadIdx.x;
    if (i >= n4) return;
    float4 v = ((const float4*)in)[i];
    uint32_t h0, m0, h1, m1;
    split2(v.x, v.y, h0, m0);
    split2(v.z, v.w, h1, m1);
    ((uint2*)hi)[i]  = make_uint2(h0, h1);
    ((uint2*)mid)[i] = make_uint2(m0, m1);
}

// ---------------------------------------------------------------------------
// NT GEMM (R9 configuration — the one inside the 1684us result).
// packed bf16 x3, ldmatrix + cp.async double buffer.
// C[M,N] = A[M,K] * B[N,K]^T. 128x128 block, BK=64 floats (32 u32),
// 512 threads = 16 warps (4m x 4n), warp tile 32x32.
// mode 0: plain fp32 store to Cp.
// mode 1: QKV epilogue — q,k: fused RoPE (heads<8) + split -> packed globals;
//         v: fp32 scatter into [B,H,T,hd].
// ---------------------------------------------------------------------------
#define GST2 36
#define G_ARR2 (128 * GST2)          // 4608 u32
#define G_STAGE2 (4 * G_ARR2)        // 18432 u32
#define S_AHI_B  0
#define S_AMID_B (G_ARR2 * 4)
#define S_BHI_B  (2 * G_ARR2 * 4)
#define S_BMID_B (3 * G_ARR2 * 4)
#define GEMM_SMEM_BYTES (2 * G_STAGE2 * 4)   // 147456

__global__ __launch_bounds__(512, 1)
void gemm_nt_tc_kernel(const uint32_t* __restrict__ Ahi, const uint32_t* __restrict__ Amid,
                       const uint32_t* __restrict__ Bhi, const uint32_t* __restrict__ Bmid,
                       const float* __restrict__ cosT, const float* __restrict__ sinT,
                       uint32_t* __restrict__ Qh, uint32_t* __restrict__ Qm,
                       uint32_t* __restrict__ Kh, uint32_t* __restrict__ Km,
                       float* __restrict__ Vp, float* __restrict__ Cp,
                       int M, int N, int K, int mode)
{
    extern __shared__ uint32_t gsm[];
    const uint32_t smem_base = (uint32_t)__cvta_generic_to_shared(gsm);

    const int tid  = threadIdx.x;
    const int lane = tid & 31;
    const int wid  = tid >> 5;
    const int g    = lane >> 2;
    const int c    = lane & 3;
    const int warp_m = (wid & 3) * 32;
    const int warp_n = (wid >> 2) * 32;

    const int bm = blockIdx.y * 128;
    const int bn = blockIdx.x * 128;
    const int Ku = K >> 1;

    const uint32_t* AhiB  = Ahi  + (size_t)bm * Ku;
    const uint32_t* AmidB = Amid + (size_t)bm * Ku;
    const uint32_t* BhiB  = Bhi  + (size_t)bn * Ku;
    const uint32_t* BmidB = Bmid + (size_t)bn * Ku;

    float acc[2][4][4];
#pragma unroll
    for (int mi = 0; mi < 2; mi++)
#pragma unroll
        for (int ni = 0; ni < 4; ni++)
#pragma unroll
            for (int e = 0; e < 4; e++) acc[mi][ni][e] = 0.0f;

    const int KT = K >> 6;

    auto load_stage = [&](int kt, int st) {
        char* dst = (char*)gsm + (size_t)st * (G_STAGE2 * 4);
        int ko = kt << 5;
#pragma unroll
        for (int l = 0; l < 2; l++) {
            int idx = tid + l * 512;
            int row = idx >> 3;
            int c4  = (idx & 7) << 2;
            size_t go = (size_t)row * Ku + ko + c4;
            uint32_t so = row * (GST2 * 4) + c4 * 4;
            cp_async16(dst + S_AHI_B  + so, AhiB  + go);
            cp_async16(dst + S_AMID_B + so, AmidB + go);
            cp_async16(dst + S_BHI_B  + so, BhiB  + go);
            cp_async16(dst + S_BMID_B + so, BmidB + go);
        }
    };

    // ldmatrix lane offsets (bytes)
    const uint32_t a_off = (uint32_t)(warp_m + (lane & 15)) * (GST2 * 4) + ((lane >> 4) << 4);
    const uint32_t b_off = (uint32_t)(warp_n + (lane & 7)) * (GST2 * 4) + (((lane >> 3) & 1) << 4);

    load_stage(0, 0);
    cp_commit();

    for (int kt = 0; kt < KT; kt++) {
        if (kt + 1 < KT) {
            load_stage(kt + 1, (kt + 1) & 1);
            cp_commit();
            cp_wait<1>();
        } else {
            cp_wait<0>();
        }
        __syncthreads();

        const uint32_t st_base = smem_base + (uint32_t)(kt & 1) * (G_STAGE2 * 4);

#pragma unroll
        for (int kk2 = 0; kk2 < 32; kk2 += 8) {
            const uint32_t kb = kk2 * 4;
            uint32_t a_h[2][4], a_m[2][4];
            ldm_x4(a_h[0], st_base + S_AHI_B  + a_off + kb);
            ldm_x4(a_h[1], st_base + S_AHI_B  + a_off + 16 * (GST2 * 4) + kb);
            ldm_x4(a_m[0], st_base + S_AMID_B + a_off + kb);
            ldm_x4(a_m[1], st_base + S_AMID_B + a_off + 16 * (GST2 * 4) + kb);
            uint32_t b_h[4][2], b_m[4][2];
#pragma unroll
            for (int ni = 0; ni < 4; ni++) {
                uint32_t ad = st_base + b_off + ni * 8 * (GST2 * 4) + kb;
                ldm_x2(b_h[ni][0], b_h[ni][1], ad + S_BHI_B);
                ldm_x2(b_m[ni][0], b_m[ni][1], ad + S_BMID_B);
            }
#pragma unroll
            for (int mi = 0; mi < 2; mi++)
#pragma unroll
                for (int ni = 0; ni < 4; ni++) {
                    mma_bf16(acc[mi][ni],
                             a_h[mi][0], a_h[mi][1], a_h[mi][2], a_h[mi][3],
                             b_h[ni][0], b_h[ni][1]);
                    mma_bf16(acc[mi][ni],
                             a_h[mi][0], a_h[mi][1], a_h[mi][2], a_h[mi][3],
                             b_m[ni][0], b_m[ni][1]);
                    mma_bf16(acc[mi][ni],
                             a_m[mi][0], a_m[mi][1], a_m[mi][2], a_m[mi][3],
                             b_h[ni][0], b_h[ni][1]);
                }
        }
        __syncthreads();
    }

    if (mode == 0) {
#pragma unroll
        for (int mi = 0; mi < 2; mi++)
#pragma unroll
            for (int ni = 0; ni < 4; ni++) {
                int row0 = bm + warp_m + mi * 16 + g;
                int col  = bn + warp_n + ni * 8 + 2 * c;
                *(float2*)(Cp + (size_t)row0 * N + col) =
                    make_float2(acc[mi][ni][0], acc[mi][ni][1]);
                *(float2*)(Cp + (size_t)(row0 + 8) * N + col) =
                    make_float2(acc[mi][ni][2], acc[mi][ni][3]);
            }
    } else {
#pragma unroll
        for (int mi = 0; mi < 2; mi++)
#pragma unroll
            for (int ni = 0; ni < 4; ni++) {
                int colg   = bn + warp_n + ni * 8 + 2 * c;
                int region = colg >> 11;          // 0=q,1=k,2=v
                int h      = (colg & 2047) >> 7;
                int hc     = colg & 127;
                int p      = hc >> 1;
#pragma unroll
                for (int half = 0; half < 2; half++) {
                    int ig = bm + warp_m + mi * 16 + g + half * 8;   // b*SEQ + t
                    int b  = ig >> 11;
                    int t  = ig & 2047;
                    float v0 = acc[mi][ni][2 * half];
                    float v1 = acc[mi][ni][2 * half + 1];
                    if (region < 2) {
                        float re = v0, im = v1;
                        if (h < NHEADS / 2) {
                            float c0 = cosT[t * 64 + p];
                            float s0 = sinT[t * 64 + p];
                            re = v0 * c0 - v1 * s0;
                            im = v0 * s0 + v1 * c0;
                        }
                        uint32_t hi, mid;
                        split2(re, im, hi, mid);
                        size_t idx = (((size_t)b * NHEADS + h) * SEQ + t) * 64 + p;
                        if (region == 0) { Qh[idx] = hi; Qm[idx] = mid; }
                        else             { Kh[idx] = hi; Km[idx] = mid; }
                    } else {
                        float* pv = Vp + (((size_t)b * NHEADS + h) * SEQ + t) * HDIM + hc;
                        *(float2*)pv = make_float2(v0, v1);
                    }
                }
            }
    }
}

// ---------------------------------------------------------------------------
// V transpose + split: g_v[bh][t][d] -> vt[bh][d][t/2] packed bf16 pairs.
// ---------------------------------------------------------------------------
__global__ __launch_bounds__(256)
void vt_split_kernel(const float* __restrict__ v,
                     uint32_t* __restrict__ vthi, uint32_t* __restrict__ vtmid)
{
    __shared__ float tile[64 * 129];
    const int bhh   = blockIdx.x;
    const int chunk = blockIdx.y;
    const int tid   = threadIdx.x;

    const float* vb = v + ((size_t)bhh * SEQ + chunk * 64) * HDIM;
#pragma unroll
    for (int l = 0; l < 8; l++) {
        int slot = tid + l * 256;
        int row  = slot >> 5;
        int c4   = (slot & 31) << 2;
        float4 val = *(const float4*)(vb + row * HDIM + c4);
        tile[row * 129 + c4 + 0] = val.x;
        tile[row * 129 + c4 + 1] = val.y;
        tile[row * 129 + c4 + 2] = val.z;
        tile[row * 129 + c4 + 3] = val.w;
    }
    __syncthreads();
#pragma unroll
    for (int l = 0; l < 16; l++) {
        int slot = tid + l * 256;
        int d  = slot >> 5;
        int sp = slot & 31;
        float f0 = tile[(2 * sp)     * 129 + d];
        float f1 = tile[(2 * sp + 1) * 129 + d];
        uint32_t hi, mid;
        split2(f0, f1, hi, mid);
        size_t idx = ((size_t)bhh * 128 + d) * (SEQ / 2) + chunk * 32 + sp;
        vthi[idx]  = hi;
        vtmid[idx] = mid;
    }
}

// ---------------------------------------------------------------------------
// Flash attention (R10 softmax-diet version — the variable under test).
// packed inputs, cp.async double buffer, ldmatrix, bf16 x3.
// Per-thread redundant m/alpha tracking; P stored packed bf16 hi/mid and
// fragment-loaded with ldmatrix in PV. 4 barriers/iter.
// Block: (b*h, q-tile of 64). 256 threads = 8 warps: wm=wid&3, wn=wid>>2.
// ---------------------------------------------------------------------------
#define QK2A 68
#define VT2A 36
#define PSP  36                // packed Ps row stride (u32)
#define OFF_QHI   0
#define OFF_QMID  4352
#define OFF_KST   8704         // + st*8704 ; hi +0, mid +4352
#define K_ST_SZ   8704
#define OFF_VST   26112        // + st*9216 ; hi +0, mid +4608
#define V_ST_SZ   9216
#define OFF_PSH   44544
#define OFF_PSM   46848
#define OFF_PMAX  49152        // 128 floats
#define OFF_LP    49280        // 128 floats
#define ATT_SMEM_U32 49408     // 197632 bytes

__global__ __launch_bounds__(256, 1)
void attn_tc_kernel(const uint32_t* __restrict__ qhiG, const uint32_t* __restrict__ qmidG,
                    const uint32_t* __restrict__ khiG, const uint32_t* __restrict__ kmidG,
                    const uint32_t* __restrict__ vthiG, const uint32_t* __restrict__ vtmidG,
                    uint32_t* __restrict__ outHi, uint32_t* __restrict__ outMid)
{
    extern __shared__ uint32_t smu[];
    const uint32_t smem_base = (uint32_t)__cvta_generic_to_shared(smu);
    float* pmax = (float*)(smu + OFF_PMAX);
    float* l_p  = (float*)(smu + OFF_LP);

    const int tid  = threadIdx.x;
    const int lane = tid & 31;
    const int wid  = tid >> 5;
    const int g    = lane >> 2;
    const int c    = lane & 3;
    const int wm   = wid & 3;
    const int wn   = wid >> 2;

    const int bh = blockIdx.y;
    const int qt = (int)gridDim.x - 1 - (int)blockIdx.x;   // heavy tiles first
    const int h  = bh & (NHEADS - 1);
    const int b  = bh >> 4;

    const float scale = 0.08838834764831845f;   // 1/sqrt(128)
    const int row0 = wm * 16 + g;
    const int row1 = row0 + 8;

    // --- load Q tile (packed) ---
    {
        const uint32_t* qh = qhiG  + ((size_t)bh * SEQ + qt * 64) * 64;
        const uint32_t* qm = qmidG + ((size_t)bh * SEQ + qt * 64) * 64;
#pragma unroll
        for (int l = 0; l < 4; l++) {
            int slot = tid + l * 256;
            int row  = slot >> 4;
            int q4   = (slot & 15) << 2;
            *(uint4*)(smu + OFF_QHI  + row * QK2A + q4) = *(const uint4*)(qh + row * 64 + q4);
            *(uint4*)(smu + OFF_QMID + row * QK2A + q4) = *(const uint4*)(qm + row * 64 + q4);
        }
    }

    auto load_kv = [&](int j, int st) {
        const uint32_t* kh = khiG  + ((size_t)bh * SEQ + j * 64) * 64;
        const uint32_t* km = kmidG + ((size_t)bh * SEQ + j * 64) * 64;
        uint32_t* kd = smu + OFF_KST + st * K_ST_SZ;
#pragma unroll
        for (int l = 0; l < 4; l++) {
            int slot = tid + l * 256;
            int row  = slot >> 4;
            int q4   = (slot & 15) << 2;
            cp_async16(kd + row * QK2A + q4,        kh + row * 64 + q4);
            cp_async16(kd + 4352 + row * QK2A + q4, km + row * 64 + q4);
        }
        const uint32_t* vh = vthiG  + (size_t)bh * 128 * (SEQ / 2);
        const uint32_t* vm = vtmidG + (size_t)bh * 128 * (SEQ / 2);
        uint32_t* vd = smu + OFF_VST + st * V_ST_SZ;
#pragma unroll
        for (int l = 0; l < 4; l++) {
            int slot = tid + l * 256;
            int d  = slot >> 3;
            int q4 = (slot & 7) << 2;
            cp_async16(vd + d * VT2A + q4,        vh + (size_t)d * (SEQ / 2) + j * 32 + q4);
            cp_async16(vd + 4608 + d * VT2A + q4, vm + (size_t)d * (SEQ / 2) + j * 32 + q4);
        }
    };

    float o[8][4];
#pragma unroll
    for (int ni = 0; ni < 8; ni++)
#pragma unroll
        for (int e = 0; e < 4; e++) o[ni][e] = 0.0f;
    float m0r = -1e30f, m1r = -1e30f;
    float l0r = 0.0f,   l1r = 0.0f;

    // ldmatrix lane offsets (bytes)
    const uint32_t qa_off = (uint32_t)(wm * 16 + (lane & 15)) * (QK2A * 4) + ((lane >> 4) << 4);
    const uint32_t kb_off = (uint32_t)(wn * 32 + (lane & 7)) * (QK2A * 4) + (((lane >> 3) & 1) << 4);
    const uint32_t vb_off = (uint32_t)(wn * 64 + (lane & 7)) * (VT2A * 4) + (((lane >> 3) & 1) << 4);
    const uint32_t pa_off = (uint32_t)(wm * 16 + (lane & 15)) * (PSP * 4) + ((lane >> 4) << 4);

    load_kv(0, 0);
    cp_commit();

    for (int j = 0; j <= qt; j++) {
        const int st = j & 1;
        if (j < qt) {
            load_kv(j + 1, st ^ 1);
            cp_commit();
            cp_wait<1>();
        } else {
            cp_wait<0>();
        }
        __syncthreads();                      // (1) tiles ready

        // --- S = Q K^T ---
        float s[4][4];
#pragma unroll
        for (int ni = 0; ni < 4; ni++)
#pragma unroll
            for (int e = 0; e < 4; e++) s[ni][e] = 0.0f;

        const uint32_t kstb = smem_base + (OFF_KST + st * K_ST_SZ) * 4;
#pragma unroll
        for (int kk2 = 0; kk2 < 64; kk2 += 8) {
            const uint32_t kb = kk2 * 4;
            uint32_t ah[4], am[4];
            ldm_x4(ah, smem_base + OFF_QHI * 4 + qa_off + kb);
            ldm_x4(am, smem_base + OFF_QMID * 4 + qa_off + kb);
#pragma unroll
            for (int ni = 0; ni < 4; ni++) {
                uint32_t ad = kstb + kb_off + ni * 8 * (QK2A * 4) + kb;
                uint32_t bh0, bh1, bm0, bm1;
                ldm_x2(bh0, bh1, ad);
                ldm_x2(bm0, bm1, ad + 4352 * 4);
                mma_bf16(s[ni], ah[0], ah[1], ah[2], ah[3], bh0, bh1);
                mma_bf16(s[ni], ah[0], ah[1], ah[2], ah[3], bm0, bm1);
                mma_bf16(s[ni], am[0], am[1], am[2], am[3], bh0, bh1);
            }
        }

        // --- scale + causal mask ---
        const bool diag = (j == qt);
#pragma unroll
        for (int ni = 0; ni < 4; ni++) {
            int colb = wn * 32 + ni * 8 + 2 * c;
#pragma unroll
            for (int e = 0; e < 4; e++) {
                int col = colb + (e & 1);
                int row = (e < 2) ? row0 : row1;
                float val = s[ni][e] * scale;
                if (diag && col > row) val = -1e30f;
                s[ni][e] = val;
            }
        }

        // --- partial row max over this warp's 32 cols ---
        float mx0 = -1e30f, mx1 = -1e30f;
#pragma unroll
        for (int ni = 0; ni < 4; ni++) {
            mx0 = fmaxf(mx0, fmaxf(s[ni][0], s[ni][1]));
            mx1 = fmaxf(mx1, fmaxf(s[ni][2], s[ni][3]));
        }
#pragma unroll
        for (int off = 1; off < 4; off <<= 1) {
            mx0 = fmaxf(mx0, __shfl_xor_sync(0xffffffffu, mx0, off));
            mx1 = fmaxf(mx1, __shfl_xor_sync(0xffffffffu, mx1, off));
        }
        if (c == 0) {
            pmax[row0 * 2 + wn] = mx0;
            pmax[row1 * 2 + wn] = mx1;
        }
        __syncthreads();                      // (2) pmax visible

        // --- per-thread redundant m update ---
        float mn0 = fmaxf(m0r, fmaxf(pmax[row0 * 2], pmax[row0 * 2 + 1]));
        float mn1 = fmaxf(m1r, fmaxf(pmax[row1 * 2], pmax[row1 * 2 + 1]));
        float a0 = __expf(m0r - mn0);
        float a1 = __expf(m1r - mn1);
        m0r = mn0; m1r = mn1;

        // --- exp, packed P store, local l partials; alpha-rescale O ---
        float rs0 = 0.0f, rs1 = 0.0f;
#pragma unroll
        for (int ni = 0; ni < 4; ni++) {
            int pair = wn * 16 + ni * 4 + c;
            float p0 = __expf(s[ni][0] - mn0);
            float p1 = __expf(s[ni][1] - mn0);
            float p2 = __expf(s[ni][2] - mn1);
            float p3 = __expf(s[ni][3] - mn1);
            rs0 += p0 + p1; rs1 += p2 + p3;
            uint32_t hi, mid;
            split2(p0, p1, hi, mid);
            smu[OFF_PSH + row0 * PSP + pair] = hi;
            smu[OFF_PSM + row0 * PSP + pair] = mid;
            split2(p2, p3, hi, mid);
            smu[OFF_PSH + row1 * PSP + pair] = hi;
            smu[OFF_PSM + row1 * PSP + pair] = mid;
        }
        l0r = l0r * a0 + rs0;
        l1r = l1r * a1 + rs1;
#pragma unroll
        for (int ni = 0; ni < 8; ni++) {
            o[ni][0] *= a0; o[ni][1] *= a0;
            o[ni][2] *= a1; o[ni][3] *= a1;
        }
        __syncthreads();                      // (3) P visible

        // --- O += P V ---
        const uint32_t vstb = smem_base + (OFF_VST + st * V_ST_SZ) * 4;
#pragma unroll
        for (int kks = 0; kks < 64; kks += 16) {
            uint32_t ph[4], pm_[4];
            ldm_x4(ph,  smem_base + OFF_PSH * 4 + pa_off + kks * 2);
            ldm_x4(pm_, smem_base + OFF_PSM * 4 + pa_off + kks * 2);
            const uint32_t kb = (kks >> 1) * 4;
#pragma unroll
            for (int ni = 0; ni < 8; ni++) {
                uint32_t ad = vstb + vb_off + ni * 8 * (VT2A * 4) + kb;
                uint32_t bh0, bh1, bm0, bm1;
                ldm_x2(bh0, bh1, ad);
                ldm_x2(bm0, bm1, ad + 4608 * 4);
                mma_bf16(o[ni], ph[0], ph[1], ph[2], ph[3], bh0, bh1);
                mma_bf16(o[ni], ph[0], ph[1], ph[2], ph[3], bm0, bm1);
                mma_bf16(o[ni], pm_[0], pm_[1], pm_[2], pm_[3], bh0, bh1);
            }
        }
        __syncthreads();                      // (4) stage/Ps reuse safe
    }

    // --- l reduction: quad shuffle then cross-warp via smem ---
#pragma unroll
    for (int off = 1; off < 4; off <<= 1) {
        l0r += __shfl_xor_sync(0xffffffffu, l0r, off);
        l1r += __shfl_xor_sync(0xffffffffu, l1r, off);
    }
    if (c == 0) {
        l_p[row0 * 2 + wn] = l0r;
        l_p[row1 * 2 + wn] = l1r;
    }
    __syncthreads();
    float il0 = 1.0f / (l_p[row0 * 2] + l_p[row0 * 2 + 1]);
    float il1 = 1.0f / (l_p[row1 * 2] + l_p[row1 * 2 + 1]);

    size_t grow0 = (size_t)b * SEQ + qt * 64 + row0;
    size_t grow1 = (size_t)b * SEQ + qt * 64 + row1;
#pragma unroll
    for (int ni = 0; ni < 8; ni++) {
        int col  = wn * 64 + ni * 8 + 2 * c;
        int pidx = h * 64 + (col >> 1);
        uint32_t hi, mid;
        split2(o[ni][0] * il0, o[ni][1] * il0, hi, mid);
        outHi [grow0 * (DMODEL / 2) + pidx] = hi;
        outMid[grow0 * (DMODEL / 2) + pidx] = mid;
        split2(o[ni][2] * il1, o[ni][3] * il1, hi, mid);
        outHi [grow1 * (DMODEL / 2) + pidx] = hi;
        outMid[grow1 * (DMODEL / 2) + pidx] = mid;
    }
}

// ---------------------------------------------------------------------------
extern "C" void kernel_launch(void* const* d_in, const int* in_sizes, int n_in,
                              void* d_out, int out_size)
{
    const float* x    = (const float*)d_in[0];   // [2,2048,2048]
    const float* Wqkv = (const float*)d_in[1];   // [6144,2048]
    const float* Wout = (const float*)d_in[2];   // [2048,2048]
    const float* cosT = (const float*)d_in[3];   // [2048,64]
    const float* sinT = (const float*)d_in[4];   // [2048,64]
    float* out = (float*)d_out;                  // [2,2048,2048]
    (void)in_sizes; (void)n_in; (void)out_size;

    float* gv;
    uint32_t *ahi, *amid, *bhi, *bmid, *whi, *wmid;
    uint32_t *qhi, *qmid, *khi, *kmid, *vthi, *vtmid;
    cudaGetSymbolAddress((void**)&gv,    g_v);
    cudaGetSymbolAddress((void**)&ahi,   g_ahi);
    cudaGetSymbolAddress((void**)&amid,  g_amid);
    cudaGetSymbolAddress((void**)&bhi,   g_bhi);
    cudaGetSymbolAddress((void**)&bmid,  g_bmid);
    cudaGetSymbolAddress((void**)&whi,   g_whi);
    cudaGetSymbolAddress((void**)&wmid,  g_wmid);
    cudaGetSymbolAddress((void**)&qhi,   g_qhi);
    cudaGetSymbolAddress((void**)&qmid,  g_qmid);
    cudaGetSymbolAddress((void**)&khi,   g_khi);
    cudaGetSymbolAddress((void**)&kmid,  g_kmid);
    cudaGetSymbolAddress((void**)&vthi,  g_vthi);
    cudaGetSymbolAddress((void**)&vtmid, g_vtmid);

    const int attn_smem = ATT_SMEM_U32 * (int)sizeof(uint32_t);   // 197632
    cudaFuncSetAttribute(gemm_nt_tc_kernel,
                         cudaFuncAttributeMaxDynamicSharedMemorySize, GEMM_SMEM_BYTES);
    cudaFuncSetAttribute(attn_tc_kernel,
                         cudaFuncAttributeMaxDynamicSharedMemorySize, attn_smem);

    // 1-3) splits first so ncu (-s 5) profiles the QKV GEMM next
    split_kernel<<<(BT * DMODEL / 4 + 255) / 256, 256>>>(x, ahi, amid, BT * DMODEL / 4);
    split_kernel<<<(3 * DMODEL * DMODEL / 4 + 255) / 256, 256>>>(Wqkv, bhi, bmid,
                                                                 3 * DMODEL * DMODEL / 4);
    split_kernel<<<(DMODEL * DMODEL / 4 + 255) / 256, 256>>>(Wout, whi, wmid,
                                                             DMODEL * DMODEL / 4);

    // 4) QKV projection (R9 config: 128x128 tile, 512 threads)
    gemm_nt_tc_kernel<<<dim3(48, 32), 512, GEMM_SMEM_BYTES>>>(
        ahi, amid, bhi, bmid, cosT, sinT,
        qhi, qmid, khi, kmid, gv, nullptr, BT, 3 * DMODEL, DMODEL, 1);

    // 5) V transpose + split into packed Vt
    vt_split_kernel<<<dim3(BATCH * NHEADS, SEQ / 64), 256>>>(gv, vthi, vtmid);

    // 6) Causal flash attention (R10 softmax-diet version — variable under test)
    attn_tc_kernel<<<dim3(SEQ / 64, BATCH * NHEADS), 256, attn_smem>>>(
        qhi, qmid, khi, kmid, vthi, vtmid, ahi, amid);

    // 7) Output projection into d_out
    gemm_nt_tc_kernel<<<dim3(16, 32), 512, GEMM_SMEM_BYTES>>>(
        ahi, amid, whi, wmid, nullptr, nullptr,
        nullptr, nullptr, nullptr, nullptr, nullptr, out, BT, DMODEL, DMODEL, 0);
}

// round 14
// speedup vs baseline: 1.4025x; 1.0021x over previous
#include <cuda_runtime.h>
#include <cuda_bf16.h>
#include <cstdint>
#include <cstddef>

#define BATCH   2
#define SEQ     2048
#define DMODEL  2048
#define NHEADS  16
#define HDIM    128
#define BT      (BATCH * SEQ)   // 4096

// Scratch (device globals — allocation-free per harness rules).
static __device__ float    g_v[(size_t)BATCH * NHEADS * SEQ * HDIM];
// packed bf16 hi/mid (2 bf16 per u32)
static __device__ uint32_t g_ahi [(size_t)BT * DMODEL / 2];
static __device__ uint32_t g_amid[(size_t)BT * DMODEL / 2];
static __device__ uint32_t g_bhi [(size_t)3 * DMODEL * DMODEL / 2];
static __device__ uint32_t g_bmid[(size_t)3 * DMODEL * DMODEL / 2];
static __device__ uint32_t g_whi [(size_t)DMODEL * DMODEL / 2];
static __device__ uint32_t g_wmid[(size_t)DMODEL * DMODEL / 2];
static __device__ uint32_t g_qhi [(size_t)BATCH * NHEADS * SEQ * (HDIM / 2)];
static __device__ uint32_t g_qmid[(size_t)BATCH * NHEADS * SEQ * (HDIM / 2)];
static __device__ uint32_t g_khi [(size_t)BATCH * NHEADS * SEQ * (HDIM / 2)];
static __device__ uint32_t g_kmid[(size_t)BATCH * NHEADS * SEQ * (HDIM / 2)];
static __device__ uint32_t g_vthi [(size_t)BATCH * NHEADS * HDIM * (SEQ / 2)];
static __device__ uint32_t g_vtmid[(size_t)BATCH * NHEADS * HDIM * (SEQ / 2)];

// ---------------------------------------------------------------------------
// bf16 helpers
// ---------------------------------------------------------------------------
__device__ __forceinline__ uint32_t pack_bf16(float f_lo, float f_hi) {
    uint32_t r;
    asm("cvt.rn.bf16x2.f32 %0, %1, %2;" : "=r"(r) : "f"(f_hi), "f"(f_lo));
    return r;
}
__device__ __forceinline__ float2 unpack_bf16(uint32_t u) {
    __nv_bfloat162 h = *reinterpret_cast<__nv_bfloat162*>(&u);
    return make_float2(__bfloat162float(h.x), __bfloat162float(h.y));  // x = low
}
__device__ __forceinline__ void split2(float f0, float f1, uint32_t& hi, uint32_t& mid) {
    hi = pack_bf16(f0, f1);
    float2 hf = unpack_bf16(hi);
    mid = pack_bf16(f0 - hf.x, f1 - hf.y);
}

__device__ __forceinline__ void mma_bf16(float d[4],
                                         uint32_t a0, uint32_t a1, uint32_t a2, uint32_t a3,
                                         uint32_t b0, uint32_t b1) {
    asm volatile(
        "mma.sync.aligned.m16n8k16.row.col.f32.bf16.bf16.f32 "
        "{%0,%1,%2,%3}, {%4,%5,%6,%7}, {%8,%9}, {%0,%1,%2,%3};"
        : "+f"(d[0]), "+f"(d[1]), "+f"(d[2]), "+f"(d[3])
        : "r"(a0), "r"(a1), "r"(a2), "r"(a3), "r"(b0), "r"(b1));
}

__device__ __forceinline__ void ldm_x4(uint32_t a[4], uint32_t addr) {
    asm volatile("ldmatrix.sync.aligned.m8n8.x4.shared.b16 {%0,%1,%2,%3}, [%4];"
                 : "=r"(a[0]), "=r"(a[1]), "=r"(a[2]), "=r"(a[3]) : "r"(addr));
}
__device__ __forceinline__ void ldm_x2(uint32_t& b0, uint32_t& b1, uint32_t addr) {
    asm volatile("ldmatrix.sync.aligned.m8n8.x2.shared.b16 {%0,%1}, [%2];"
                 : "=r"(b0), "=r"(b1) : "r"(addr));
}

__device__ __forceinline__ void cp_async16(void* smem_dst, const void* gmem_src) {
    uint32_t s = (uint32_t)__cvta_generic_to_shared(smem_dst);
    asm volatile("cp.async.cg.shared.global [%0], [%1], 16;" :: "r"(s), "l"(gmem_src));
}
__device__ __forceinline__ void cp_commit() { asm volatile("cp.async.commit_group;"); }
template <int N>
__device__ __forceinline__ void cp_wait() {
    asm volatile("cp.async.wait_group %0;" :: "n"(N));
}

// ---------------------------------------------------------------------------
// Split kernel: float array -> packed bf16 (hi, mid) arrays.
// ---------------------------------------------------------------------------
__global__ void split_kernel(const float* __restrict__ in,
                             uint32_t* __restrict__ hi, uint32_t* __restrict__ mid,
                             int n4)
{
    int i = blockIdx.x * blockDim.x + threadIdx.x;
    if (i >= n4) return;
    float4 v = ((const float4*)in)[i];
    uint32_t h0, m0, h1, m1;
    split2(v.x, v.y, h0, m0);
    split2(v.z, v.w, h1, m1);
    ((uint2*)hi)[i]  = make_uint2(h0, h1);
    ((uint2*)mid)[i] = make_uint2(m0, m1);
}

// ---------------------------------------------------------------------------
// NT GEMM, packed bf16 x3, ldmatrix + cp.async THREE-stage ring (1 barrier
// per stage — the tail barrier is removed; buffer (kt+2)%3 was last read by
// the MMA of stage kt-1, which every warp finished before the barrier at the
// top of iter kt, after which the kt+2 loads are issued).
// C[M,N] = A[M,K] * B[N,K]^T. 128x128 block, BK=64 floats (32 u32),
// 512 threads = 16 warps (4m x 4n), warp tile 32x32.
// mode 0: plain fp32 store to Cp.
// mode 1: QKV epilogue — q,k: fused RoPE (heads<8) + split -> packed globals;
//         v: fp32 scatter into [B,H,T,hd].
// ---------------------------------------------------------------------------
#define GST2 36
#define G_ARR2 (128 * GST2)          // 4608 u32
#define G_STAGE2 (4 * G_ARR2)        // 18432 u32 = 73728 B
#define S_AHI_B  0
#define S_AMID_B (G_ARR2 * 4)
#define S_BHI_B  (2 * G_ARR2 * 4)
#define S_BMID_B (3 * G_ARR2 * 4)
#define GEMM_SMEM_BYTES (3 * G_STAGE2 * 4)   // 221184

__global__ __launch_bounds__(512, 1)
void gemm_nt_tc_kernel(const uint32_t* __restrict__ Ahi, const uint32_t* __restrict__ Amid,
                       const uint32_t* __restrict__ Bhi, const uint32_t* __restrict__ Bmid,
                       const float* __restrict__ cosT, const float* __restrict__ sinT,
                       uint32_t* __restrict__ Qh, uint32_t* __restrict__ Qm,
                       uint32_t* __restrict__ Kh, uint32_t* __restrict__ Km,
                       float* __restrict__ Vp, float* __restrict__ Cp,
                       int M, int N, int K, int mode)
{
    extern __shared__ uint32_t gsm[];
    const uint32_t smem_base = (uint32_t)__cvta_generic_to_shared(gsm);

    const int tid  = threadIdx.x;
    const int lane = tid & 31;
    const int wid  = tid >> 5;
    const int g    = lane >> 2;
    const int c    = lane & 3;
    const int warp_m = (wid & 3) * 32;
    const int warp_n = (wid >> 2) * 32;

    const int bm = blockIdx.y * 128;
    const int bn = blockIdx.x * 128;
    const int Ku = K >> 1;

    const uint32_t* AhiB  = Ahi  + (size_t)bm * Ku;
    const uint32_t* AmidB = Amid + (size_t)bm * Ku;
    const uint32_t* BhiB  = Bhi  + (size_t)bn * Ku;
    const uint32_t* BmidB = Bmid + (size_t)bn * Ku;

    float acc[2][4][4];
#pragma unroll
    for (int mi = 0; mi < 2; mi++)
#pragma unroll
        for (int ni = 0; ni < 4; ni++)
#pragma unroll
            for (int e = 0; e < 4; e++) acc[mi][ni][e] = 0.0f;

    const int KT = K >> 6;

    auto load_stage = [&](int kt, int st) {
        char* dst = (char*)gsm + (size_t)st * (G_STAGE2 * 4);
        int ko = kt << 5;
#pragma unroll
        for (int l = 0; l < 2; l++) {
            int idx = tid + l * 512;
            int row = idx >> 3;
            int c4  = (idx & 7) << 2;
            size_t go = (size_t)row * Ku + ko + c4;
            uint32_t so = row * (GST2 * 4) + c4 * 4;
            cp_async16(dst + S_AHI_B  + so, AhiB  + go);
            cp_async16(dst + S_AMID_B + so, AmidB + go);
            cp_async16(dst + S_BHI_B  + so, BhiB  + go);
            cp_async16(dst + S_BMID_B + so, BmidB + go);
        }
    };

    // ldmatrix lane offsets (bytes)
    const uint32_t a_off = (uint32_t)(warp_m + (lane & 15)) * (GST2 * 4) + ((lane >> 4) << 4);
    const uint32_t b_off = (uint32_t)(warp_n + (lane & 7)) * (GST2 * 4) + (((lane >> 3) & 1) << 4);

    // prologue: two stages in flight
    load_stage(0, 0);
    cp_commit();
    if (KT > 1) { load_stage(1, 1); cp_commit(); }

    for (int kt = 0; kt < KT; kt++) {
        if (kt + 1 < KT) {
            cp_wait<1>();      // stage kt resident (kt+1 may still fly)
        } else {
            cp_wait<0>();
        }
        __syncthreads();       // stage kt visible to all; stage kt-1 MMA done by all

        // prefetch stage kt+2 into the ring slot last read at stage kt-1
        if (kt + 2 < KT) {
            load_stage(kt + 2, (kt + 2) % 3);
            cp_commit();
        }

        const uint32_t st_base = smem_base + (uint32_t)(kt % 3) * (G_STAGE2 * 4);

#pragma unroll
        for (int kk2 = 0; kk2 < 32; kk2 += 8) {
            const uint32_t kb = kk2 * 4;
            uint32_t a_h[2][4], a_m[2][4];
            ldm_x4(a_h[0], st_base + S_AHI_B  + a_off + kb);
            ldm_x4(a_h[1], st_base + S_AHI_B  + a_off + 16 * (GST2 * 4) + kb);
            ldm_x4(a_m[0], st_base + S_AMID_B + a_off + kb);
            ldm_x4(a_m[1], st_base + S_AMID_B + a_off + 16 * (GST2 * 4) + kb);
            uint32_t b_h[4][2], b_m[4][2];
#pragma unroll
            for (int ni = 0; ni < 4; ni++) {
                uint32_t ad = st_base + b_off + ni * 8 * (GST2 * 4) + kb;
                ldm_x2(b_h[ni][0], b_h[ni][1], ad + S_BHI_B);
                ldm_x2(b_m[ni][0], b_m[ni][1], ad + S_BMID_B);
            }
#pragma unroll
            for (int mi = 0; mi < 2; mi++)
#pragma unroll
                for (int ni = 0; ni < 4; ni++) {
                    mma_bf16(acc[mi][ni],
                             a_h[mi][0], a_h[mi][1], a_h[mi][2], a_h[mi][3],
                             b_h[ni][0], b_h[ni][1]);
                    mma_bf16(acc[mi][ni],
                             a_h[mi][0], a_h[mi][1], a_h[mi][2], a_h[mi][3],
                             b_m[ni][0], b_m[ni][1]);
                    mma_bf16(acc[mi][ni],
                             a_m[mi][0], a_m[mi][1], a_m[mi][2], a_m[mi][3],
                             b_h[ni][0], b_h[ni][1]);
                }
        }
        // no tail barrier — 3-stage ring makes buffer reuse safe via the
        // top-of-next-iteration barrier
    }

    if (mode == 0) {
#pragma unroll
        for (int mi = 0; mi < 2; mi++)
#pragma unroll
            for (int ni = 0; ni < 4; ni++) {
                int row0 = bm + warp_m + mi * 16 + g;
                int col  = bn + warp_n + ni * 8 + 2 * c;
                *(float2*)(Cp + (size_t)row0 * N + col) =
                    make_float2(acc[mi][ni][0], acc[mi][ni][1]);
                *(float2*)(Cp + (size_t)(row0 + 8) * N + col) =
                    make_float2(acc[mi][ni][2], acc[mi][ni][3]);
            }
    } else {
#pragma unroll
        for (int mi = 0; mi < 2; mi++)
#pragma unroll
            for (int ni = 0; ni < 4; ni++) {
                int colg   = bn + warp_n + ni * 8 + 2 * c;
                int region = colg >> 11;          // 0=q,1=k,2=v
                int h      = (colg & 2047) >> 7;
                int hc     = colg & 127;
                int p      = hc >> 1;
#pragma unroll
                for (int half = 0; half < 2; half++) {
                    int ig = bm + warp_m + mi * 16 + g + half * 8;   // b*SEQ + t
                    int b  = ig >> 11;
                    int t  = ig & 2047;
                    float v0 = acc[mi][ni][2 * half];
                    float v1 = acc[mi][ni][2 * half + 1];
                    if (region < 2) {
                        float re = v0, im = v1;
                        if (h < NHEADS / 2) {
                            float c0 = cosT[t * 64 + p];
                            float s0 = sinT[t * 64 + p];
                            re = v0 * c0 - v1 * s0;
                            im = v0 * s0 + v1 * c0;
                        }
                        uint32_t hi, mid;
                        split2(re, im, hi, mid);
                        size_t idx = (((size_t)b * NHEADS + h) * SEQ + t) * 64 + p;
                        if (region == 0) { Qh[idx] = hi; Qm[idx] = mid; }
                        else             { Kh[idx] = hi; Km[idx] = mid; }
                    } else {
                        float* pv = Vp + (((size_t)b * NHEADS + h) * SEQ + t) * HDIM + hc;
                        *(float2*)pv = make_float2(v0, v1);
                    }
                }
            }
    }
}

// ---------------------------------------------------------------------------
// V transpose + split: g_v[bh][t][d] -> vt[bh][d][t/2] packed bf16 pairs.
// ---------------------------------------------------------------------------
__global__ __launch_bounds__(256)
void vt_split_kernel(const float* __restrict__ v,
                     uint32_t* __restrict__ vthi, uint32_t* __restrict__ vtmid)
{
    __shared__ float tile[64 * 129];
    const int bhh   = blockIdx.x;
    const int chunk = blockIdx.y;
    const int tid   = threadIdx.x;

    const float* vb = v + ((size_t)bhh * SEQ + chunk * 64) * HDIM;
#pragma unroll
    for (int l = 0; l < 8; l++) {
        int slot = tid + l * 256;
        int row  = slot >> 5;
        int c4   = (slot & 31) << 2;
        float4 val = *(const float4*)(vb + row * HDIM + c4);
        tile[row * 129 + c4 + 0] = val.x;
        tile[row * 129 + c4 + 1] = val.y;
        tile[row * 129 + c4 + 2] = val.z;
        tile[row * 129 + c4 + 3] = val.w;
    }
    __syncthreads();
#pragma unroll
    for (int l = 0; l < 16; l++) {
        int slot = tid + l * 256;
        int d  = slot >> 5;
        int sp = slot & 31;
        float f0 = tile[(2 * sp)     * 129 + d];
        float f1 = tile[(2 * sp + 1) * 129 + d];
        uint32_t hi, mid;
        split2(f0, f1, hi, mid);
        size_t idx = ((size_t)bhh * 128 + d) * (SEQ / 2) + chunk * 32 + sp;
        vthi[idx]  = hi;
        vtmid[idx] = mid;
    }
}

// ---------------------------------------------------------------------------
// Flash attention (R12 version, unchanged): packed inputs, cp.async double
// buffer, ldmatrix, bf16 x3; per-thread redundant softmax state; packed P.
// ---------------------------------------------------------------------------
#define QK2A 68
#define VT2A 36
#define PSP  36                // packed Ps row stride (u32)
#define OFF_QHI   0
#define OFF_QMID  4352
#define OFF_KST   8704         // + st*8704 ; hi +0, mid +4352
#define K_ST_SZ   8704
#define OFF_VST   26112        // + st*9216 ; hi +0, mid +4608
#define V_ST_SZ   9216
#define OFF_PSH   44544
#define OFF_PSM   46848
#define OFF_PMAX  49152        // 128 floats
#define OFF_LP    49280        // 128 floats
#define ATT_SMEM_U32 49408     // 197632 bytes

__global__ __launch_bounds__(256, 1)
void attn_tc_kernel(const uint32_t* __restrict__ qhiG, const uint32_t* __restrict__ qmidG,
                    const uint32_t* __restrict__ khiG, const uint32_t* __restrict__ kmidG,
                    const uint32_t* __restrict__ vthiG, const uint32_t* __restrict__ vtmidG,
                    uint32_t* __restrict__ outHi, uint32_t* __restrict__ outMid)
{
    extern __shared__ uint32_t smu[];
    const uint32_t smem_base = (uint32_t)__cvta_generic_to_shared(smu);
    float* pmax = (float*)(smu + OFF_PMAX);
    float* l_p  = (float*)(smu + OFF_LP);

    const int tid  = threadIdx.x;
    const int lane = tid & 31;
    const int wid  = tid >> 5;
    const int g    = lane >> 2;
    const int c    = lane & 3;
    const int wm   = wid & 3;
    const int wn   = wid >> 2;

    const int bh = blockIdx.y;
    const int qt = (int)gridDim.x - 1 - (int)blockIdx.x;   // heavy tiles first
    const int h  = bh & (NHEADS - 1);
    const int b  = bh >> 4;

    const float scale = 0.08838834764831845f;   // 1/sqrt(128)
    const int row0 = wm * 16 + g;
    const int row1 = row0 + 8;

    // --- load Q tile (packed) ---
    {
        const uint32_t* qh = qhiG  + ((size_t)bh * SEQ + qt * 64) * 64;
        const uint32_t* qm = qmidG + ((size_t)bh * SEQ + qt * 64) * 64;
#pragma unroll
        for (int l = 0; l < 4; l++) {
            int slot = tid + l * 256;
            int row  = slot >> 4;
            int q4   = (slot & 15) << 2;
            *(uint4*)(smu + OFF_QHI  + row * QK2A + q4) = *(const uint4*)(qh + row * 64 + q4);
            *(uint4*)(smu + OFF_QMID + row * QK2A + q4) = *(const uint4*)(qm + row * 64 + q4);
        }
    }

    auto load_kv = [&](int j, int st) {
        const uint32_t* kh = khiG  + ((size_t)bh * SEQ + j * 64) * 64;
        const uint32_t* km = kmidG + ((size_t)bh * SEQ + j * 64) * 64;
        uint32_t* kd = smu + OFF_KST + st * K_ST_SZ;
#pragma unroll
        for (int l = 0; l < 4; l++) {
            int slot = tid + l * 256;
            int row  = slot >> 4;
            int q4   = (slot & 15) << 2;
            cp_async16(kd + row * QK2A + q4,        kh + row * 64 + q4);
            cp_async16(kd + 4352 + row * QK2A + q4, km + row * 64 + q4);
        }
        const uint32_t* vh = vthiG  + (size_t)bh * 128 * (SEQ / 2);
        const uint32_t* vm = vtmidG + (size_t)bh * 128 * (SEQ / 2);
        uint32_t* vd = smu + OFF_VST + st * V_ST_SZ;
#pragma unroll
        for (int l = 0; l < 4; l++) {
            int slot = tid + l * 256;
            int d  = slot >> 3;
            int q4 = (slot & 7) << 2;
            cp_async16(vd + d * VT2A + q4,        vh + (size_t)d * (SEQ / 2) + j * 32 + q4);
            cp_async16(vd + 4608 + d * VT2A + q4, vm + (size_t)d * (SEQ / 2) + j * 32 + q4);
        }
    };

    float o[8][4];
#pragma unroll
    for (int ni = 0; ni < 8; ni++)
#pragma unroll
        for (int e = 0; e < 4; e++) o[ni][e] = 0.0f;
    float m0r = -1e30f, m1r = -1e30f;
    float l0r = 0.0f,   l1r = 0.0f;

    // ldmatrix lane offsets (bytes)
    const uint32_t qa_off = (uint32_t)(wm * 16 + (lane & 15)) * (QK2A * 4) + ((lane >> 4) << 4);
    const uint32_t kb_off = (uint32_t)(wn * 32 + (lane & 7)) * (QK2A * 4) + (((lane >> 3) & 1) << 4);
    const uint32_t vb_off = (uint32_t)(wn * 64 + (lane & 7)) * (VT2A * 4) + (((lane >> 3) & 1) << 4);
    const uint32_t pa_off = (uint32_t)(wm * 16 + (lane & 15)) * (PSP * 4) + ((lane >> 4) << 4);

    load_kv(0, 0);
    cp_commit();

    for (int j = 0; j <= qt; j++) {
        const int st = j & 1;
        if (j < qt) {
            load_kv(j + 1, st ^ 1);
            cp_commit();
            cp_wait<1>();
        } else {
            cp_wait<0>();
        }
        __syncthreads();                      // (1) tiles ready

        // --- S = Q K^T ---
        float s[4][4];
#pragma unroll
        for (int ni = 0; ni < 4; ni++)
#pragma unroll
            for (int e = 0; e < 4; e++) s[ni][e] = 0.0f;

        const uint32_t kstb = smem_base + (OFF_KST + st * K_ST_SZ) * 4;
#pragma unroll
        for (int kk2 = 0; kk2 < 64; kk2 += 8) {
            const uint32_t kb = kk2 * 4;
            uint32_t ah[4], am[4];
            ldm_x4(ah, smem_base + OFF_QHI * 4 + qa_off + kb);
            ldm_x4(am, smem_base + OFF_QMID * 4 + qa_off + kb);
#pragma unroll
            for (int ni = 0; ni < 4; ni++) {
                uint32_t ad = kstb + kb_off + ni * 8 * (QK2A * 4) + kb;
                uint32_t bh0, bh1, bm0, bm1;
                ldm_x2(bh0, bh1, ad);
                ldm_x2(bm0, bm1, ad + 4352 * 4);
                mma_bf16(s[ni], ah[0], ah[1], ah[2], ah[3], bh0, bh1);
                mma_bf16(s[ni], ah[0], ah[1], ah[2], ah[3], bm0, bm1);
                mma_bf16(s[ni], am[0], am[1], am[2], am[3], bh0, bh1);
            }
        }

        // --- scale + causal mask ---
        const bool diag = (j == qt);
#pragma unroll
        for (int ni = 0; ni < 4; ni++) {
            int colb = wn * 32 + ni * 8 + 2 * c;
#pragma unroll
            for (int e = 0; e < 4; e++) {
                int col = colb + (e & 1);
                int row = (e < 2) ? row0 : row1;
                float val = s[ni][e] * scale;
                if (diag && col > row) val = -1e30f;
                s[ni][e] = val;
            }
        }

        // --- partial row max over this warp's 32 cols ---
        float mx0 = -1e30f, mx1 = -1e30f;
#pragma unroll
        for (int ni = 0; ni < 4; ni++) {
            mx0 = fmaxf(mx0, fmaxf(s[ni][0], s[ni][1]));
            mx1 = fmaxf(mx1, fmaxf(s[ni][2], s[ni][3]));
        }
#pragma unroll
        for (int off = 1; off < 4; off <<= 1) {
            mx0 = fmaxf(mx0, __shfl_xor_sync(0xffffffffu, mx0, off));
            mx1 = fmaxf(mx1, __shfl_xor_sync(0xffffffffu, mx1, off));
        }
        if (c == 0) {
            pmax[row0 * 2 + wn] = mx0;
            pmax[row1 * 2 + wn] = mx1;
        }
        __syncthreads();                      // (2) pmax visible

        // --- per-thread redundant m update ---
        float mn0 = fmaxf(m0r, fmaxf(pmax[row0 * 2], pmax[row0 * 2 + 1]));
        float mn1 = fmaxf(m1r, fmaxf(pmax[row1 * 2], pmax[row1 * 2 + 1]));
        float a0 = __expf(m0r - mn0);
        float a1 = __expf(m1r - mn1);
        m0r = mn0; m1r = mn1;

        // --- exp, packed P store, local l partials; alpha-rescale O ---
        float rs0 = 0.0f, rs1 = 0.0f;
#pragma unroll
        for (int ni = 0; ni < 4; ni++) {
            int pair = wn * 16 + ni * 4 + c;
            float p0 = __expf(s[ni][0] - mn0);
            float p1 = __expf(s[ni][1] - mn0);
            float p2 = __expf(s[ni][2] - mn1);
            float p3 = __expf(s[ni][3] - mn1);
            rs0 += p0 + p1; rs1 += p2 + p3;
            uint32_t hi, mid;
            split2(p0, p1, hi, mid);
            smu[OFF_PSH + row0 * PSP + pair] = hi;
            smu[OFF_PSM + row0 * PSP + pair] = mid;
            split2(p2, p3, hi, mid);
            smu[OFF_PSH + row1 * PSP + pair] = hi;
            smu[OFF_PSM + row1 * PSP + pair] = mid;
        }
        l0r = l0r * a0 + rs0;
        l1r = l1r * a1 + rs1;
#pragma unroll
        for (int ni = 0; ni < 8; ni++) {
            o[ni][0] *= a0; o[ni][1] *= a0;
            o[ni][2] *= a1; o[ni][3] *= a1;
        }
        __syncthreads();                      // (3) P visible

        // --- O += P V ---
        const uint32_t vstb = smem_base + (OFF_VST + st * V_ST_SZ) * 4;
#pragma unroll
        for (int kks = 0; kks < 64; kks += 16) {
            uint32_t ph[4], pm_[4];
            ldm_x4(ph,  smem_base + OFF_PSH * 4 + pa_off + kks * 2);
            ldm_x4(pm_, smem_base + OFF_PSM * 4 + pa_off + kks * 2);
            const uint32_t kb = (kks >> 1) * 4;
#pragma unroll
            for (int ni = 0; ni < 8; ni++) {
                uint32_t ad = vstb + vb_off + ni * 8 * (VT2A * 4) + kb;
                uint32_t bh0, bh1, bm0, bm1;
                ldm_x2(bh0, bh1, ad);
                ldm_x2(bm0, bm1, ad + 4608 * 4);
                mma_bf16(o[ni], ph[0], ph[1], ph[2], ph[3], bh0, bh1);
                mma_bf16(o[ni], ph[0], ph[1], ph[2], ph[3], bm0, bm1);
                mma_bf16(o[ni], pm_[0], pm_[1], pm_[2], pm_[3], bh0, bh1);
            }
        }
        __syncthreads();                      // (4) stage/Ps reuse safe
    }

    // --- l reduction: quad shuffle then cross-warp via smem ---
#pragma unroll
    for (int off = 1; off < 4; off <<= 1) {
        l0r += __shfl_xor_sync(0xffffffffu, l0r, off);
        l1r += __shfl_xor_sync(0xffffffffu, l1r, off);
    }
    if (c == 0) {
        l_p[row0 * 2 + wn] = l0r;
        l_p[row1 * 2 + wn] = l1r;
    }
    __syncthreads();
    float il0 = 1.0f / (l_p[row0 * 2] + l_p[row0 * 2 + 1]);
    float il1 = 1.0f / (l_p[row1 * 2] + l_p[row1 * 2 + 1]);

    size_t grow0 = (size_t)b * SEQ + qt * 64 + row0;
    size_t grow1 = (size_t)b * SEQ + qt * 64 + row1;
#pragma unroll
    for (int ni = 0; ni < 8; ni++) {
        int col  = wn * 64 + ni * 8 + 2 * c;
        int pidx = h * 64 + (col >> 1);
        uint32_t hi, mid;
        split2(o[ni][0] * il0, o[ni][1] * il0, hi, mid);
        outHi [grow0 * (DMODEL / 2) + pidx] = hi;
        outMid[grow0 * (DMODEL / 2) + pidx] = mid;
        split2(o[ni][2] * il1, o[ni][3] * il1, hi, mid);
        outHi [grow1 * (DMODEL / 2) + pidx] = hi;
        outMid[grow1 * (DMODEL / 2) + pidx] = mid;
    }
}

// ---------------------------------------------------------------------------
extern "C" void kernel_launch(void* const* d_in, const int* in_sizes, int n_in,
                              void* d_out, int out_size)
{
    const float* x    = (const float*)d_in[0];   // [2,2048,2048]
    const float* Wqkv = (const float*)d_in[1];   // [6144,2048]
    const float* Wout = (const float*)d_in[2];   // [2048,2048]
    const float* cosT = (const float*)d_in[3];   // [2048,64]
    const float* sinT = (const float*)d_in[4];   // [2048,64]
    float* out = (float*)d_out;                  // [2,2048,2048]
    (void)in_sizes; (void)n_in; (void)out_size;

    float* gv;
    uint32_t *ahi, *amid, *bhi, *bmid, *whi, *wmid;
    uint32_t *qhi, *qmid, *khi, *kmid, *vthi, *vtmid;
    cudaGetSymbolAddress((void**)&gv,    g_v);
    cudaGetSymbolAddress((void**)&ahi,   g_ahi);
    cudaGetSymbolAddress((void**)&amid,  g_amid);
    cudaGetSymbolAddress((void**)&bhi,   g_bhi);
    cudaGetSymbolAddress((void**)&bmid,  g_bmid);
    cudaGetSymbolAddress((void**)&whi,   g_whi);
    cudaGetSymbolAddress((void**)&wmid,  g_wmid);
    cudaGetSymbolAddress((void**)&qhi,   g_qhi);
    cudaGetSymbolAddress((void**)&qmid,  g_qmid);
    cudaGetSymbolAddress((void**)&khi,   g_khi);
    cudaGetSymbolAddress((void**)&kmid,  g_kmid);
    cudaGetSymbolAddress((void**)&vthi,  g_vthi);
    cudaGetSymbolAddress((void**)&vtmid, g_vtmid);

    const int attn_smem = ATT_SMEM_U32 * (int)sizeof(uint32_t);   // 197632
    cudaFuncSetAttribute(gemm_nt_tc_kernel,
                         cudaFuncAttributeMaxDynamicSharedMemorySize, GEMM_SMEM_BYTES);
    cudaFuncSetAttribute(attn_tc_kernel,
                         cudaFuncAttributeMaxDynamicSharedMemorySize, attn_smem);

    // 1-3) splits first so ncu (-s 5) profiles the QKV GEMM next
    split_kernel<<<(BT * DMODEL / 4 + 255) / 256, 256>>>(x, ahi, amid, BT * DMODEL / 4);
    split_kernel<<<(3 * DMODEL * DMODEL / 4 + 255) / 256, 256>>>(Wqkv, bhi, bmid,
                                                                 3 * DMODEL * DMODEL / 4);
    split_kernel<<<(DMODEL * DMODEL / 4 + 255) / 256, 256>>>(Wout, whi, wmid,
                                                             DMODEL * DMODEL / 4);

    // 4) QKV projection (3-stage pipeline)
    gemm_nt_tc_kernel<<<dim3(48, 32), 512, GEMM_SMEM_BYTES>>>(
        ahi, amid, bhi, bmid, cosT, sinT,
        qhi, qmid, khi, kmid, gv, nullptr, BT, 3 * DMODEL, DMODEL, 1);

    // 5) V transpose + split into packed Vt
    vt_split_kernel<<<dim3(BATCH * NHEADS, SEQ / 64), 256>>>(gv, vthi, vtmid);

    // 6) Causal flash attention
    attn_tc_kernel<<<dim3(SEQ / 64, BATCH * NHEADS), 256, attn_smem>>>(
        qhi, qmid, khi, kmid, vthi, vtmid, ahi, amid);

    // 7) Output projection into d_out
    gemm_nt_tc_kernel<<<dim3(16, 32), 512, GEMM_SMEM_BYTES>>>(
        ahi, amid, whi, wmid, nullptr, nullptr,
        nullptr, nullptr, nullptr, nullptr, nullptr, out, BT, DMODEL, DMODEL, 0);
}

// round 15
// speedup vs baseline: 1.4041x; 1.0011x over previous
#include <cuda_runtime.h>
#include <cuda_bf16.h>
#include <cstdint>
#include <cstddef>

#define BATCH   2
#define SEQ     2048
#define DMODEL  2048
#define NHEADS  16
#define HDIM    128
#define BT      (BATCH * SEQ)   // 4096

// Scratch (device globals — allocation-free per harness rules).
static __device__ float    g_v[(size_t)BATCH * NHEADS * SEQ * HDIM];
// packed bf16 hi/mid (2 bf16 per u32)
static __device__ uint32_t g_ahi [(size_t)BT * DMODEL / 2];
static __device__ uint32_t g_amid[(size_t)BT * DMODEL / 2];
static __device__ uint32_t g_bhi [(size_t)3 * DMODEL * DMODEL / 2];
static __device__ uint32_t g_bmid[(size_t)3 * DMODEL * DMODEL / 2];
static __device__ uint32_t g_whi [(size_t)DMODEL * DMODEL / 2];
static __device__ uint32_t g_wmid[(size_t)DMODEL * DMODEL / 2];
static __device__ uint32_t g_qhi [(size_t)BATCH * NHEADS * SEQ * (HDIM / 2)];
static __device__ uint32_t g_qmid[(size_t)BATCH * NHEADS * SEQ * (HDIM / 2)];
static __device__ uint32_t g_khi [(size_t)BATCH * NHEADS * SEQ * (HDIM / 2)];
static __device__ uint32_t g_kmid[(size_t)BATCH * NHEADS * SEQ * (HDIM / 2)];
static __device__ uint32_t g_vthi [(size_t)BATCH * NHEADS * HDIM * (SEQ / 2)];
static __device__ uint32_t g_vtmid[(size_t)BATCH * NHEADS * HDIM * (SEQ / 2)];

// ---------------------------------------------------------------------------
// bf16 helpers
// ---------------------------------------------------------------------------
__device__ __forceinline__ uint32_t pack_bf16(float f_lo, float f_hi) {
    uint32_t r;
    asm("cvt.rn.bf16x2.f32 %0, %1, %2;" : "=r"(r) : "f"(f_hi), "f"(f_lo));
    return r;
}
__device__ __forceinline__ float2 unpack_bf16(uint32_t u) {
    __nv_bfloat162 h = *reinterpret_cast<__nv_bfloat162*>(&u);
    return make_float2(__bfloat162float(h.x), __bfloat162float(h.y));  // x = low
}
__device__ __forceinline__ void split2(float f0, float f1, uint32_t& hi, uint32_t& mid) {
    hi = pack_bf16(f0, f1);
    float2 hf = unpack_bf16(hi);
    mid = pack_bf16(f0 - hf.x, f1 - hf.y);
}

__device__ __forceinline__ void mma_bf16(float d[4],
                                         uint32_t a0, uint32_t a1, uint32_t a2, uint32_t a3,
                                         uint32_t b0, uint32_t b1) {
    asm volatile(
        "mma.sync.aligned.m16n8k16.row.col.f32.bf16.bf16.f32 "
        "{%0,%1,%2,%3}, {%4,%5,%6,%7}, {%8,%9}, {%0,%1,%2,%3};"
        : "+f"(d[0]), "+f"(d[1]), "+f"(d[2]), "+f"(d[3])
        : "r"(a0), "r"(a1), "r"(a2), "r"(a3), "r"(b0), "r"(b1));
}

__device__ __forceinline__ void ldm_x4(uint32_t a[4], uint32_t addr) {
    asm volatile("ldmatrix.sync.aligned.m8n8.x4.shared.b16 {%0,%1,%2,%3}, [%4];"
                 : "=r"(a[0]), "=r"(a[1]), "=r"(a[2]), "=r"(a[3]) : "r"(addr));
}
__device__ __forceinline__ void ldm_x2(uint32_t& b0, uint32_t& b1, uint32_t addr) {
    asm volatile("ldmatrix.sync.aligned.m8n8.x2.shared.b16 {%0,%1}, [%2];"
                 : "=r"(b0), "=r"(b1) : "r"(addr));
}

__device__ __forceinline__ void cp_async16(void* smem_dst, const void* gmem_src) {
    uint32_t s = (uint32_t)__cvta_generic_to_shared(smem_dst);
    asm volatile("cp.async.cg.shared.global [%0], [%1], 16;" :: "r"(s), "l"(gmem_src));
}
__device__ __forceinline__ void cp_commit() { asm volatile("cp.async.commit_group;"); }
template <int N>
__device__ __forceinline__ void cp_wait() {
    asm volatile("cp.async.wait_group %0;" :: "n"(N));
}

// ---------------------------------------------------------------------------
// Split kernel: float array -> packed bf16 (hi, mid) arrays.
// ---------------------------------------------------------------------------
__global__ void split_kernel(const float* __restrict__ in,
                             uint32_t* __restrict__ hi, uint32_t* __restrict__ mid,
                             int n4)
{
    int i = blockIdx.x * blockDim.x + threadIdx.x;
    if (i >= n4) return;
    float4 v = ((const float4*)in)[i];
    uint32_t h0, m0, h1, m1;
    split2(v.x, v.y, h0, m0);
    split2(v.z, v.w, h1, m1);
    ((uint2*)hi)[i]  = make_uint2(h0, h1);
    ((uint2*)mid)[i] = make_uint2(m0, m1);
}

// ---------------------------------------------------------------------------
// NT GEMM, packed bf16 x3, ldmatrix + cp.async 3-stage ring.
// TERM-MAJOR MMA ORDER: consecutive MMAs hit different accumulators, breaking
// the 3-deep accumulator RAW chains (asm volatile pins PTX order, so this is
// the only way to separate dependent HMMAs). Per-accumulator term order is
// still hh -> hm -> mh, so results are bit-identical to R13.
// C[M,N] = A[M,K] * B[N,K]^T. 128x128 block, BK=64 floats (32 u32),
// 512 threads = 16 warps (4m x 4n), warp tile 32x32.
// mode 0: plain fp32 store.  mode 1: QKV epilogue (RoPE+split q,k; fp32 v).
// ---------------------------------------------------------------------------
#define GST2 36
#define G_ARR2 (128 * GST2)          // 4608 u32
#define G_STAGE2 (4 * G_ARR2)        // 18432 u32 = 73728 B
#define S_AHI_B  0
#define S_AMID_B (G_ARR2 * 4)
#define S_BHI_B  (2 * G_ARR2 * 4)
#define S_BMID_B (3 * G_ARR2 * 4)
#define GEMM_SMEM_BYTES (3 * G_STAGE2 * 4)   // 221184

__global__ __launch_bounds__(512, 1)
void gemm_nt_tc_kernel(const uint32_t* __restrict__ Ahi, const uint32_t* __restrict__ Amid,
                       const uint32_t* __restrict__ Bhi, const uint32_t* __restrict__ Bmid,
                       const float* __restrict__ cosT, const float* __restrict__ sinT,
                       uint32_t* __restrict__ Qh, uint32_t* __restrict__ Qm,
                       uint32_t* __restrict__ Kh, uint32_t* __restrict__ Km,
                       float* __restrict__ Vp, float* __restrict__ Cp,
                       int M, int N, int K, int mode)
{
    extern __shared__ uint32_t gsm[];
    const uint32_t smem_base = (uint32_t)__cvta_generic_to_shared(gsm);

    const int tid  = threadIdx.x;
    const int lane = tid & 31;
    const int wid  = tid >> 5;
    const int g    = lane >> 2;
    const int c    = lane & 3;
    const int warp_m = (wid & 3) * 32;
    const int warp_n = (wid >> 2) * 32;

    const int bm = blockIdx.y * 128;
    const int bn = blockIdx.x * 128;
    const int Ku = K >> 1;

    const uint32_t* AhiB  = Ahi  + (size_t)bm * Ku;
    const uint32_t* AmidB = Amid + (size_t)bm * Ku;
    const uint32_t* BhiB  = Bhi  + (size_t)bn * Ku;
    const uint32_t* BmidB = Bmid + (size_t)bn * Ku;

    float acc[2][4][4];
#pragma unroll
    for (int mi = 0; mi < 2; mi++)
#pragma unroll
        for (int ni = 0; ni < 4; ni++)
#pragma unroll
            for (int e = 0; e < 4; e++) acc[mi][ni][e] = 0.0f;

    const int KT = K >> 6;

    auto load_stage = [&](int kt, int st) {
        char* dst = (char*)gsm + (size_t)st * (G_STAGE2 * 4);
        int ko = kt << 5;
#pragma unroll
        for (int l = 0; l < 2; l++) {
            int idx = tid + l * 512;
            int row = idx >> 3;
            int c4  = (idx & 7) << 2;
            size_t go = (size_t)row * Ku + ko + c4;
            uint32_t so = row * (GST2 * 4) + c4 * 4;
            cp_async16(dst + S_AHI_B  + so, AhiB  + go);
            cp_async16(dst + S_AMID_B + so, AmidB + go);
            cp_async16(dst + S_BHI_B  + so, BhiB  + go);
            cp_async16(dst + S_BMID_B + so, BmidB + go);
        }
    };

    // ldmatrix lane offsets (bytes)
    const uint32_t a_off = (uint32_t)(warp_m + (lane & 15)) * (GST2 * 4) + ((lane >> 4) << 4);
    const uint32_t b_off = (uint32_t)(warp_n + (lane & 7)) * (GST2 * 4) + (((lane >> 3) & 1) << 4);

    // prologue: two stages in flight
    load_stage(0, 0);
    cp_commit();
    if (KT > 1) { load_stage(1, 1); cp_commit(); }

    for (int kt = 0; kt < KT; kt++) {
        if (kt + 1 < KT) {
            cp_wait<1>();
        } else {
            cp_wait<0>();
        }
        __syncthreads();

        if (kt + 2 < KT) {
            load_stage(kt + 2, (kt + 2) % 3);
            cp_commit();
        }

        const uint32_t st_base = smem_base + (uint32_t)(kt % 3) * (G_STAGE2 * 4);

#pragma unroll
        for (int kk2 = 0; kk2 < 32; kk2 += 8) {
            const uint32_t kb = kk2 * 4;
            uint32_t a_h[2][4], a_m[2][4];
            ldm_x4(a_h[0], st_base + S_AHI_B  + a_off + kb);
            ldm_x4(a_h[1], st_base + S_AHI_B  + a_off + 16 * (GST2 * 4) + kb);
            ldm_x4(a_m[0], st_base + S_AMID_B + a_off + kb);
            ldm_x4(a_m[1], st_base + S_AMID_B + a_off + 16 * (GST2 * 4) + kb);
            uint32_t b_h[4][2], b_m[4][2];
#pragma unroll
            for (int ni = 0; ni < 4; ni++) {
                uint32_t ad = st_base + b_off + ni * 8 * (GST2 * 4) + kb;
                ldm_x2(b_h[ni][0], b_h[ni][1], ad + S_BHI_B);
                ldm_x2(b_m[ni][0], b_m[ni][1], ad + S_BMID_B);
            }
            // term-major: 8 independent accumulators between same-acc reuses
#pragma unroll
            for (int mi = 0; mi < 2; mi++)
#pragma unroll
                for (int ni = 0; ni < 4; ni++)
                    mma_bf16(acc[mi][ni],
                             a_h[mi][0], a_h[mi][1], a_h[mi][2], a_h[mi][3],
                             b_h[ni][0], b_h[ni][1]);
#pragma unroll
            for (int mi = 0; mi < 2; mi++)
#pragma unroll
                for (int ni = 0; ni < 4; ni++)
                    mma_bf16(acc[mi][ni],
                             a_h[mi][0], a_h[mi][1], a_h[mi][2], a_h[mi][3],
                             b_m[ni][0], b_m[ni][1]);
#pragma unroll
            for (int mi = 0; mi < 2; mi++)
#pragma unroll
                for (int ni = 0; ni < 4; ni++)
                    mma_bf16(acc[mi][ni],
                             a_m[mi][0], a_m[mi][1], a_m[mi][2], a_m[mi][3],
                             b_h[ni][0], b_h[ni][1]);
        }
    }

    if (mode == 0) {
#pragma unroll
        for (int mi = 0; mi < 2; mi++)
#pragma unroll
            for (int ni = 0; ni < 4; ni++) {
                int row0 = bm + warp_m + mi * 16 + g;
                int col  = bn + warp_n + ni * 8 + 2 * c;
                *(float2*)(Cp + (size_t)row0 * N + col) =
                    make_float2(acc[mi][ni][0], acc[mi][ni][1]);
                *(float2*)(Cp + (size_t)(row0 + 8) * N + col) =
                    make_float2(acc[mi][ni][2], acc[mi][ni][3]);
            }
    } else {
#pragma unroll
        for (int mi = 0; mi < 2; mi++)
#pragma unroll
            for (int ni = 0; ni < 4; ni++) {
                int colg   = bn + warp_n + ni * 8 + 2 * c;
                int region = colg >> 11;          // 0=q,1=k,2=v
                int h      = (colg & 2047) >> 7;
                int hc     = colg & 127;
                int p      = hc >> 1;
#pragma unroll
                for (int half = 0; half < 2; half++) {
                    int ig = bm + warp_m + mi * 16 + g + half * 8;   // b*SEQ + t
                    int b  = ig >> 11;
                    int t  = ig & 2047;
                    float v0 = acc[mi][ni][2 * half];
                    float v1 = acc[mi][ni][2 * half + 1];
                    if (region < 2) {
                        float re = v0, im = v1;
                        if (h < NHEADS / 2) {
                            float c0 = cosT[t * 64 + p];
                            float s0 = sinT[t * 64 + p];
                            re = v0 * c0 - v1 * s0;
                            im = v0 * s0 + v1 * c0;
                        }
                        uint32_t hi, mid;
                        split2(re, im, hi, mid);
                        size_t idx = (((size_t)b * NHEADS + h) * SEQ + t) * 64 + p;
                        if (region == 0) { Qh[idx] = hi; Qm[idx] = mid; }
                        else             { Kh[idx] = hi; Km[idx] = mid; }
                    } else {
                        float* pv = Vp + (((size_t)b * NHEADS + h) * SEQ + t) * HDIM + hc;
                        *(float2*)pv = make_float2(v0, v1);
                    }
                }
            }
    }
}

// ---------------------------------------------------------------------------
// V transpose + split: g_v[bh][t][d] -> vt[bh][d][t/2] packed bf16 pairs.
// ---------------------------------------------------------------------------
__global__ __launch_bounds__(256)
void vt_split_kernel(const float* __restrict__ v,
                     uint32_t* __restrict__ vthi, uint32_t* __restrict__ vtmid)
{
    __shared__ float tile[64 * 129];
    const int bhh   = blockIdx.x;
    const int chunk = blockIdx.y;
    const int tid   = threadIdx.x;

    const float* vb = v + ((size_t)bhh * SEQ + chunk * 64) * HDIM;
#pragma unroll
    for (int l = 0; l < 8; l++) {
        int slot = tid + l * 256;
        int row  = slot >> 5;
        int c4   = (slot & 31) << 2;
        float4 val = *(const float4*)(vb + row * HDIM + c4);
        tile[row * 129 + c4 + 0] = val.x;
        tile[row * 129 + c4 + 1] = val.y;
        tile[row * 129 + c4 + 2] = val.z;
        tile[row * 129 + c4 + 3] = val.w;
    }
    __syncthreads();
#pragma unroll
    for (int l = 0; l < 16; l++) {
        int slot = tid + l * 256;
        int d  = slot >> 5;
        int sp = slot & 31;
        float f0 = tile[(2 * sp)     * 129 + d];
        float f1 = tile[(2 * sp + 1) * 129 + d];
        uint32_t hi, mid;
        split2(f0, f1, hi, mid);
        size_t idx = ((size_t)bhh * 128 + d) * (SEQ / 2) + chunk * 32 + sp;
        vthi[idx]  = hi;
        vtmid[idx] = mid;
    }
}

// ---------------------------------------------------------------------------
// Flash attention: packed inputs, cp.async double buffer, ldmatrix, bf16 x3
// with TERM-MAJOR MMA ordering (same transform as the GEMM).
// ---------------------------------------------------------------------------
#define QK2A 68
#define VT2A 36
#define PSP  36                // packed Ps row stride (u32)
#define OFF_QHI   0
#define OFF_QMID  4352
#define OFF_KST   8704         // + st*8704 ; hi +0, mid +4352
#define K_ST_SZ   8704
#define OFF_VST   26112        // + st*9216 ; hi +0, mid +4608
#define V_ST_SZ   9216
#define OFF_PSH   44544
#define OFF_PSM   46848
#define OFF_PMAX  49152        // 128 floats
#define OFF_LP    49280        // 128 floats
#define ATT_SMEM_U32 49408     // 197632 bytes

__global__ __launch_bounds__(256, 1)
void attn_tc_kernel(const uint32_t* __restrict__ qhiG, const uint32_t* __restrict__ qmidG,
                    const uint32_t* __restrict__ khiG, const uint32_t* __restrict__ kmidG,
                    const uint32_t* __restrict__ vthiG, const uint32_t* __restrict__ vtmidG,
                    uint32_t* __restrict__ outHi, uint32_t* __restrict__ outMid)
{
    extern __shared__ uint32_t smu[];
    const uint32_t smem_base = (uint32_t)__cvta_generic_to_shared(smu);
    float* pmax = (float*)(smu + OFF_PMAX);
    float* l_p  = (float*)(smu + OFF_LP);

    const int tid  = threadIdx.x;
    const int lane = tid & 31;
    const int wid  = tid >> 5;
    const int g    = lane >> 2;
    const int c    = lane & 3;
    const int wm   = wid & 3;
    const int wn   = wid >> 2;

    const int bh = blockIdx.y;
    const int qt = (int)gridDim.x - 1 - (int)blockIdx.x;   // heavy tiles first
    const int h  = bh & (NHEADS - 1);
    const int b  = bh >> 4;

    const float scale = 0.08838834764831845f;   // 1/sqrt(128)
    const int row0 = wm * 16 + g;
    const int row1 = row0 + 8;

    // --- load Q tile (packed) ---
    {
        const uint32_t* qh = qhiG  + ((size_t)bh * SEQ + qt * 64) * 64;
        const uint32_t* qm = qmidG + ((size_t)bh * SEQ + qt * 64) * 64;
#pragma unroll
        for (int l = 0; l < 4; l++) {
            int slot = tid + l * 256;
            int row  = slot >> 4;
            int q4   = (slot & 15) << 2;
            *(uint4*)(smu + OFF_QHI  + row * QK2A + q4) = *(const uint4*)(qh + row * 64 + q4);
            *(uint4*)(smu + OFF_QMID + row * QK2A + q4) = *(const uint4*)(qm + row * 64 + q4);
        }
    }

    auto load_kv = [&](int j, int st) {
        const uint32_t* kh = khiG  + ((size_t)bh * SEQ + j * 64) * 64;
        const uint32_t* km = kmidG + ((size_t)bh * SEQ + j * 64) * 64;
        uint32_t* kd = smu + OFF_KST + st * K_ST_SZ;
#pragma unroll
        for (int l = 0; l < 4; l++) {
            int slot = tid + l * 256;
            int row  = slot >> 4;
            int q4   = (slot & 15) << 2;
            cp_async16(kd + row * QK2A + q4,        kh + row * 64 + q4);
            cp_async16(kd + 4352 + row * QK2A + q4, km + row * 64 + q4);
        }
        const uint32_t* vh = vthiG  + (size_t)bh * 128 * (SEQ / 2);
        const uint32_t* vm = vtmidG + (size_t)bh * 128 * (SEQ / 2);
        uint32_t* vd = smu + OFF_VST + st * V_ST_SZ;
#pragma unroll
        for (int l = 0; l < 4; l++) {
            int slot = tid + l * 256;
            int d  = slot >> 3;
            int q4 = (slot & 7) << 2;
            cp_async16(vd + d * VT2A + q4,        vh + (size_t)d * (SEQ / 2) + j * 32 + q4);
            cp_async16(vd + 4608 + d * VT2A + q4, vm + (size_t)d * (SEQ / 2) + j * 32 + q4);
        }
    };

    float o[8][4];
#pragma unroll
    for (int ni = 0; ni < 8; ni++)
#pragma unroll
        for (int e = 0; e < 4; e++) o[ni][e] = 0.0f;
    float m0r = -1e30f, m1r = -1e30f;
    float l0r = 0.0f,   l1r = 0.0f;

    // ldmatrix lane offsets (bytes)
    const uint32_t qa_off = (uint32_t)(wm * 16 + (lane & 15)) * (QK2A * 4) + ((lane >> 4) << 4);
    const uint32_t kb_off = (uint32_t)(wn * 32 + (lane & 7)) * (QK2A * 4) + (((lane >> 3) & 1) << 4);
    const uint32_t vb_off = (uint32_t)(wn * 64 + (lane & 7)) * (VT2A * 4) + (((lane >> 3) & 1) << 4);
    const uint32_t pa_off = (uint32_t)(wm * 16 + (lane & 15)) * (PSP * 4) + ((lane >> 4) << 4);

    load_kv(0, 0);
    cp_commit();

    for (int j = 0; j <= qt; j++) {
        const int st = j & 1;
        if (j < qt) {
            load_kv(j + 1, st ^ 1);
            cp_commit();
            cp_wait<1>();
        } else {
            cp_wait<0>();
        }
        __syncthreads();                      // (1) tiles ready

        // --- S = Q K^T (term-major) ---
        float s[4][4];
#pragma unroll
        for (int ni = 0; ni < 4; ni++)
#pragma unroll
            for (int e = 0; e < 4; e++) s[ni][e] = 0.0f;

        const uint32_t kstb = smem_base + (OFF_KST + st * K_ST_SZ) * 4;
#pragma unroll
        for (int kk2 = 0; kk2 < 64; kk2 += 8) {
            const uint32_t kb = kk2 * 4;
            uint32_t ah[4], am[4];
            ldm_x4(ah, smem_base + OFF_QHI * 4 + qa_off + kb);
            ldm_x4(am, smem_base + OFF_QMID * 4 + qa_off + kb);
            uint32_t bh_[4][2], bm_[4][2];
#pragma unroll
            for (int ni = 0; ni < 4; ni++) {
                uint32_t ad = kstb + kb_off + ni * 8 * (QK2A * 4) + kb;
                ldm_x2(bh_[ni][0], bh_[ni][1], ad);
                ldm_x2(bm_[ni][0], bm_[ni][1], ad + 4352 * 4);
            }
#pragma unroll
            for (int ni = 0; ni < 4; ni++)
                mma_bf16(s[ni], ah[0], ah[1], ah[2], ah[3], bh_[ni][0], bh_[ni][1]);
#pragma unroll
            for (int ni = 0; ni < 4; ni++)
                mma_bf16(s[ni], ah[0], ah[1], ah[2], ah[3], bm_[ni][0], bm_[ni][1]);
#pragma unroll
            for (int ni = 0; ni < 4; ni++)
                mma_bf16(s[ni], am[0], am[1], am[2], am[3], bh_[ni][0], bh_[ni][1]);
        }

        // --- scale + causal mask ---
        const bool diag = (j == qt);
#pragma unroll
        for (int ni = 0; ni < 4; ni++) {
            int colb = wn * 32 + ni * 8 + 2 * c;
#pragma unroll
            for (int e = 0; e < 4; e++) {
                int col = colb + (e & 1);
                int row = (e < 2) ? row0 : row1;
                float val = s[ni][e] * scale;
                if (diag && col > row) val = -1e30f;
                s[ni][e] = val;
            }
        }

        // --- partial row max over this warp's 32 cols ---
        float mx0 = -1e30f, mx1 = -1e30f;
#pragma unroll
        for (int ni = 0; ni < 4; ni++) {
            mx0 = fmaxf(mx0, fmaxf(s[ni][0], s[ni][1]));
            mx1 = fmaxf(mx1, fmaxf(s[ni][2], s[ni][3]));
        }
#pragma unroll
        for (int off = 1; off < 4; off <<= 1) {
            mx0 = fmaxf(mx0, __shfl_xor_sync(0xffffffffu, mx0, off));
            mx1 = fmaxf(mx1, __shfl_xor_sync(0xffffffffu, mx1, off));
        }
        if (c == 0) {
            pmax[row0 * 2 + wn] = mx0;
            pmax[row1 * 2 + wn] = mx1;
        }
        __syncthreads();                      // (2) pmax visible

        // --- per-thread redundant m update ---
        float mn0 = fmaxf(m0r, fmaxf(pmax[row0 * 2], pmax[row0 * 2 + 1]));
        float mn1 = fmaxf(m1r, fmaxf(pmax[row1 * 2], pmax[row1 * 2 + 1]));
        float a0 = __expf(m0r - mn0);
        float a1 = __expf(m1r - mn1);
        m0r = mn0; m1r = mn1;

        // --- exp, packed P store, local l partials; alpha-rescale O ---
        float rs0 = 0.0f, rs1 = 0.0f;
#pragma unroll
        for (int ni = 0; ni < 4; ni++) {
            int pair = wn * 16 + ni * 4 + c;
            float p0 = __expf(s[ni][0] - mn0);
            float p1 = __expf(s[ni][1] - mn0);
            float p2 = __expf(s[ni][2] - mn1);
            float p3 = __expf(s[ni][3] - mn1);
            rs0 += p0 + p1; rs1 += p2 + p3;
            uint32_t hi, mid;
            split2(p0, p1, hi, mid);
            smu[OFF_PSH + row0 * PSP + pair] = hi;
            smu[OFF_PSM + row0 * PSP + pair] = mid;
            split2(p2, p3, hi, mid);
            smu[OFF_PSH + row1 * PSP + pair] = hi;
            smu[OFF_PSM + row1 * PSP + pair] = mid;
        }
        l0r = l0r * a0 + rs0;
        l1r = l1r * a1 + rs1;
#pragma unroll
        for (int ni = 0; ni < 8; ni++) {
            o[ni][0] *= a0; o[ni][1] *= a0;
            o[ni][2] *= a1; o[ni][3] *= a1;
        }
        __syncthreads();                      // (3) P visible

        // --- O += P V (term-major) ---
        const uint32_t vstb = smem_base + (OFF_VST + st * V_ST_SZ) * 4;
#pragma unroll
        for (int kks = 0; kks < 64; kks += 16) {
            uint32_t ph[4], pm_[4];
            ldm_x4(ph,  smem_base + OFF_PSH * 4 + pa_off + kks * 2);
            ldm_x4(pm_, smem_base + OFF_PSM * 4 + pa_off + kks * 2);
            const uint32_t kb = (kks >> 1) * 4;
            uint32_t vh_[8][2], vm_[8][2];
#pragma unroll
            for (int ni = 0; ni < 8; ni++) {
                uint32_t ad = vstb + vb_off + ni * 8 * (VT2A * 4) + kb;
                ldm_x2(vh_[ni][0], vh_[ni][1], ad);
                ldm_x2(vm_[ni][0], vm_[ni][1], ad + 4608 * 4);
            }
#pragma unroll
            for (int ni = 0; ni < 8; ni++)
                mma_bf16(o[ni], ph[0], ph[1], ph[2], ph[3], vh_[ni][0], vh_[ni][1]);
#pragma unroll
            for (int ni = 0; ni < 8; ni++)
                mma_bf16(o[ni], ph[0], ph[1], ph[2], ph[3], vm_[ni][0], vm_[ni][1]);
#pragma unroll
            for (int ni = 0; ni < 8; ni++)
                mma_bf16(o[ni], pm_[0], pm_[1], pm_[2], pm_[3], vh_[ni][0], vh_[ni][1]);
        }
        __syncthreads();                      // (4) stage/Ps reuse safe
    }

    // --- l reduction: quad shuffle then cross-warp via smem ---
#pragma unroll
    for (int off = 1; off < 4; off <<= 1) {
        l0r += __shfl_xor_sync(0xffffffffu, l0r, off);
        l1r += __shfl_xor_sync(0xffffffffu, l1r, off);
    }
    if (c == 0) {
        l_p[row0 * 2 + wn] = l0r;
        l_p[row1 * 2 + wn] = l1r;
    }
    __syncthreads();
    float il0 = 1.0f / (l_p[row0 * 2] + l_p[row0 * 2 + 1]);
    float il1 = 1.0f / (l_p[row1 * 2] + l_p[row1 * 2 + 1]);

    size_t grow0 = (size_t)b * SEQ + qt * 64 + row0;
    size_t grow1 = (size_t)b * SEQ + qt * 64 + row1;
#pragma unroll
    for (int ni = 0; ni < 8; ni++) {
        int col  = wn * 64 + ni * 8 + 2 * c;
        int pidx = h * 64 + (col >> 1);
        uint32_t hi, mid;
        split2(o[ni][0] * il0, o[ni][1] * il0, hi, mid);
        outHi [grow0 * (DMODEL / 2) + pidx] = hi;
        outMid[grow0 * (DMODEL / 2) + pidx] = mid;
        split2(o[ni][2] * il1, o[ni][3] * il1, hi, mid);
        outHi [grow1 * (DMODEL / 2) + pidx] = hi;
        outMid[grow1 * (DMODEL / 2) + pidx] = mid;
    }
}

// ---------------------------------------------------------------------------
extern "C" void kernel_launch(void* const* d_in, const int* in_sizes, int n_in,
                              void* d_out, int out_size)
{
    const float* x    = (const float*)d_in[0];   // [2,2048,2048]
    const float* Wqkv = (const float*)d_in[1];   // [6144,2048]
    const float* Wout = (const float*)d_in[2];   // [2048,2048]
    const float* cosT = (const float*)d_in[3];   // [2048,64]
    const float* sinT = (const float*)d_in[4];   // [2048,64]
    float* out = (float*)d_out;                  // [2,2048,2048]
    (void)in_sizes; (void)n_in; (void)out_size;

    float* gv;
    uint32_t *ahi, *amid, *bhi, *bmid, *whi, *wmid;
    uint32_t *qhi, *qmid, *khi, *kmid, *vthi, *vtmid;
    cudaGetSymbolAddress((void**)&gv,    g_v);
    cudaGetSymbolAddress((void**)&ahi,   g_ahi);
    cudaGetSymbolAddress((void**)&amid,  g_amid);
    cudaGetSymbolAddress((void**)&bhi,   g_bhi);
    cudaGetSymbolAddress((void**)&bmid,  g_bmid);
    cudaGetSymbolAddress((void**)&whi,   g_whi);
    cudaGetSymbolAddress((void**)&wmid,  g_wmid);
    cudaGetSymbolAddress((void**)&qhi,   g_qhi);
    cudaGetSymbolAddress((void**)&qmid,  g_qmid);
    cudaGetSymbolAddress((void**)&khi,   g_khi);
    cudaGetSymbolAddress((void**)&kmid,  g_kmid);
    cudaGetSymbolAddress((void**)&vthi,  g_vthi);
    cudaGetSymbolAddress((void**)&vtmid, g_vtmid);

    const int attn_smem = ATT_SMEM_U32 * (int)sizeof(uint32_t);   // 197632
    cudaFuncSetAttribute(gemm_nt_tc_kernel,
                         cudaFuncAttributeMaxDynamicSharedMemorySize, GEMM_SMEM_BYTES);
    cudaFuncSetAttribute(attn_tc_kernel,
                         cudaFuncAttributeMaxDynamicSharedMemorySize, attn_smem);

    // 1-3) splits first so ncu (-s 5) profiles the QKV GEMM next
    split_kernel<<<(BT * DMODEL / 4 + 255) / 256, 256>>>(x, ahi, amid, BT * DMODEL / 4);
    split_kernel<<<(3 * DMODEL * DMODEL / 4 + 255) / 256, 256>>>(Wqkv, bhi, bmid,
                                                                 3 * DMODEL * DMODEL / 4);
    split_kernel<<<(DMODEL * DMODEL / 4 + 255) / 256, 256>>>(Wout, whi, wmid,
                                                             DMODEL * DMODEL / 4);

    // 4) QKV projection
    gemm_nt_tc_kernel<<<dim3(48, 32), 512, GEMM_SMEM_BYTES>>>(
        ahi, amid, bhi, bmid, cosT, sinT,
        qhi, qmid, khi, kmid, gv, nullptr, BT, 3 * DMODEL, DMODEL, 1);

    // 5) V transpose + split into packed Vt
    vt_split_kernel<<<dim3(BATCH * NHEADS, SEQ / 64), 256>>>(gv, vthi, vtmid);

    // 6) Causal flash attention
    attn_tc_kernel<<<dim3(SEQ / 64, BATCH * NHEADS), 256, attn_smem>>>(
        qhi, qmid, khi, kmid, vthi, vtmid, ahi, amid);

    // 7) Output projection into d_out
    gemm_nt_tc_kernel<<<dim3(16, 32), 512, GEMM_SMEM_BYTES>>>(
        ahi, amid, whi, wmid, nullptr, nullptr,
        nullptr, nullptr, nullptr, nullptr, nullptr, out, BT, DMODEL, DMODEL, 0);
}

// round 16
// speedup vs baseline: 1.4056x; 1.0010x over previous
#include <cuda_runtime.h>
#include <cuda_bf16.h>
#include <cstdint>
#include <cstddef>

#define BATCH   2
#define SEQ     2048
#define DMODEL  2048
#define NHEADS  16
#define HDIM    128
#define BT      (BATCH * SEQ)   // 4096

// Scratch (device globals — allocation-free per harness rules).
static __device__ float    g_v[(size_t)BATCH * NHEADS * SEQ * HDIM];
// packed bf16 hi/mid (2 bf16 per u32)
static __device__ uint32_t g_ahi [(size_t)BT * DMODEL / 2];
static __device__ uint32_t g_amid[(size_t)BT * DMODEL / 2];
static __device__ uint32_t g_bhi [(size_t)3 * DMODEL * DMODEL / 2];
static __device__ uint32_t g_bmid[(size_t)3 * DMODEL * DMODEL / 2];
static __device__ uint32_t g_whi [(size_t)DMODEL * DMODEL / 2];
static __device__ uint32_t g_wmid[(size_t)DMODEL * DMODEL / 2];
static __device__ uint32_t g_qhi [(size_t)BATCH * NHEADS * SEQ * (HDIM / 2)];
static __device__ uint32_t g_qmid[(size_t)BATCH * NHEADS * SEQ * (HDIM / 2)];
static __device__ uint32_t g_khi [(size_t)BATCH * NHEADS * SEQ * (HDIM / 2)];
static __device__ uint32_t g_kmid[(size_t)BATCH * NHEADS * SEQ * (HDIM / 2)];
static __device__ uint32_t g_vthi [(size_t)BATCH * NHEADS * HDIM * (SEQ / 2)];
static __device__ uint32_t g_vtmid[(size_t)BATCH * NHEADS * HDIM * (SEQ / 2)];

// ---------------------------------------------------------------------------
// bf16 helpers
// ---------------------------------------------------------------------------
__device__ __forceinline__ uint32_t pack_bf16(float f_lo, float f_hi) {
    uint32_t r;
    asm("cvt.rn.bf16x2.f32 %0, %1, %2;" : "=r"(r) : "f"(f_hi), "f"(f_lo));
    return r;
}
__device__ __forceinline__ float2 unpack_bf16(uint32_t u) {
    __nv_bfloat162 h = *reinterpret_cast<__nv_bfloat162*>(&u);
    return make_float2(__bfloat162float(h.x), __bfloat162float(h.y));  // x = low
}
__device__ __forceinline__ void split2(float f0, float f1, uint32_t& hi, uint32_t& mid) {
    hi = pack_bf16(f0, f1);
    float2 hf = unpack_bf16(hi);
    mid = pack_bf16(f0 - hf.x, f1 - hf.y);
}

// NON-VOLATILE pure-register MMA: ptxas may schedule freely (interleave with
// loads, software-pipeline across blocks). No CSE hazard: accumulator operands
// differ at every use. Results are order-identical per accumulator.
__device__ __forceinline__ void mma_bf16(float d[4],
                                         uint32_t a0, uint32_t a1, uint32_t a2, uint32_t a3,
                                         uint32_t b0, uint32_t b1) {
    asm("mma.sync.aligned.m16n8k16.row.col.f32.bf16.bf16.f32 "
        "{%0,%1,%2,%3}, {%4,%5,%6,%7}, {%8,%9}, {%0,%1,%2,%3};"
        : "+f"(d[0]), "+f"(d[1]), "+f"(d[2]), "+f"(d[3])
        : "r"(a0), "r"(a1), "r"(a2), "r"(a3), "r"(b0), "r"(b1));
}

// NON-VOLATILE ldmatrix with memory clobber: pinned against barriers and
// cp.async (which also carry memory clobbers) but MMAs can schedule around it.
__device__ __forceinline__ void ldm_x4(uint32_t a[4], uint32_t addr) {
    asm("ldmatrix.sync.aligned.m8n8.x4.shared.b16 {%0,%1,%2,%3}, [%4];"
        : "=r"(a[0]), "=r"(a[1]), "=r"(a[2]), "=r"(a[3]) : "r"(addr) : "memory");
}
__device__ __forceinline__ void ldm_x2(uint32_t& b0, uint32_t& b1, uint32_t addr) {
    asm("ldmatrix.sync.aligned.m8n8.x2.shared.b16 {%0,%1}, [%2];"
        : "=r"(b0), "=r"(b1) : "r"(addr) : "memory");
}

__device__ __forceinline__ void cp_async16(void* smem_dst, const void* gmem_src) {
    uint32_t s = (uint32_t)__cvta_generic_to_shared(smem_dst);
    asm volatile("cp.async.cg.shared.global [%0], [%1], 16;"
                 :: "r"(s), "l"(gmem_src) : "memory");
}
__device__ __forceinline__ void cp_commit() {
    asm volatile("cp.async.commit_group;" ::: "memory");
}
template <int N>
__device__ __forceinline__ void cp_wait() {
    asm volatile("cp.async.wait_group %0;" :: "n"(N) : "memory");
}

// ---------------------------------------------------------------------------
// Split kernel: float array -> packed bf16 (hi, mid) arrays.
// ---------------------------------------------------------------------------
__global__ void split_kernel(const float* __restrict__ in,
                             uint32_t* __restrict__ hi, uint32_t* __restrict__ mid,
                             int n4)
{
    int i = blockIdx.x * blockDim.x + threadIdx.x;
    if (i >= n4) return;
    float4 v = ((const float4*)in)[i];
    uint32_t h0, m0, h1, m1;
    split2(v.x, v.y, h0, m0);
    split2(v.z, v.w, h1, m1);
    ((uint2*)hi)[i]  = make_uint2(h0, h1);
    ((uint2*)mid)[i] = make_uint2(m0, m1);
}

// ---------------------------------------------------------------------------
// NT GEMM, packed bf16 x3, ldmatrix + cp.async 3-stage ring, non-volatile MMA
// asm so ptxas software-pipelines the inner loop.
// C[M,N] = A[M,K] * B[N,K]^T. 128x128 block, BK=64 floats (32 u32),
// 512 threads = 16 warps (4m x 4n), warp tile 32x32.
// mode 0: plain fp32 store.  mode 1: QKV epilogue (RoPE+split q,k; fp32 v).
// ---------------------------------------------------------------------------
#define GST2 36
#define G_ARR2 (128 * GST2)          // 4608 u32
#define G_STAGE2 (4 * G_ARR2)        // 18432 u32 = 73728 B
#define S_AHI_B  0
#define S_AMID_B (G_ARR2 * 4)
#define S_BHI_B  (2 * G_ARR2 * 4)
#define S_BMID_B (3 * G_ARR2 * 4)
#define GEMM_SMEM_BYTES (3 * G_STAGE2 * 4)   // 221184

__global__ __launch_bounds__(512, 1)
void gemm_nt_tc_kernel(const uint32_t* __restrict__ Ahi, const uint32_t* __restrict__ Amid,
                       const uint32_t* __restrict__ Bhi, const uint32_t* __restrict__ Bmid,
                       const float* __restrict__ cosT, const float* __restrict__ sinT,
                       uint32_t* __restrict__ Qh, uint32_t* __restrict__ Qm,
                       uint32_t* __restrict__ Kh, uint32_t* __restrict__ Km,
                       float* __restrict__ Vp, float* __restrict__ Cp,
                       int M, int N, int K, int mode)
{
    extern __shared__ uint32_t gsm[];
    const uint32_t smem_base = (uint32_t)__cvta_generic_to_shared(gsm);

    const int tid  = threadIdx.x;
    const int lane = tid & 31;
    const int wid  = tid >> 5;
    const int g    = lane >> 2;
    const int c    = lane & 3;
    const int warp_m = (wid & 3) * 32;
    const int warp_n = (wid >> 2) * 32;

    const int bm = blockIdx.y * 128;
    const int bn = blockIdx.x * 128;
    const int Ku = K >> 1;

    const uint32_t* AhiB  = Ahi  + (size_t)bm * Ku;
    const uint32_t* AmidB = Amid + (size_t)bm * Ku;
    const uint32_t* BhiB  = Bhi  + (size_t)bn * Ku;
    const uint32_t* BmidB = Bmid + (size_t)bn * Ku;

    float acc[2][4][4];
#pragma unroll
    for (int mi = 0; mi < 2; mi++)
#pragma unroll
        for (int ni = 0; ni < 4; ni++)
#pragma unroll
            for (int e = 0; e < 4; e++) acc[mi][ni][e] = 0.0f;

    const int KT = K >> 6;

    auto load_stage = [&](int kt, int st) {
        char* dst = (char*)gsm + (size_t)st * (G_STAGE2 * 4);
        int ko = kt << 5;
#pragma unroll
        for (int l = 0; l < 2; l++) {
            int idx = tid + l * 512;
            int row = idx >> 3;
            int c4  = (idx & 7) << 2;
            size_t go = (size_t)row * Ku + ko + c4;
            uint32_t so = row * (GST2 * 4) + c4 * 4;
            cp_async16(dst + S_AHI_B  + so, AhiB  + go);
            cp_async16(dst + S_AMID_B + so, AmidB + go);
            cp_async16(dst + S_BHI_B  + so, BhiB  + go);
            cp_async16(dst + S_BMID_B + so, BmidB + go);
        }
    };

    // ldmatrix lane offsets (bytes)
    const uint32_t a_off = (uint32_t)(warp_m + (lane & 15)) * (GST2 * 4) + ((lane >> 4) << 4);
    const uint32_t b_off = (uint32_t)(warp_n + (lane & 7)) * (GST2 * 4) + (((lane >> 3) & 1) << 4);

    // prologue: two stages in flight
    load_stage(0, 0);
    cp_commit();
    if (KT > 1) { load_stage(1, 1); cp_commit(); }

    for (int kt = 0; kt < KT; kt++) {
        if (kt + 1 < KT) {
            cp_wait<1>();
        } else {
            cp_wait<0>();
        }
        __syncthreads();

        if (kt + 2 < KT) {
            load_stage(kt + 2, (kt + 2) % 3);
            cp_commit();
        }

        const uint32_t st_base = smem_base + (uint32_t)(kt % 3) * (G_STAGE2 * 4);

#pragma unroll
        for (int kk2 = 0; kk2 < 32; kk2 += 8) {
            const uint32_t kb = kk2 * 4;
            uint32_t a_h[2][4], a_m[2][4];
            ldm_x4(a_h[0], st_base + S_AHI_B  + a_off + kb);
            ldm_x4(a_h[1], st_base + S_AHI_B  + a_off + 16 * (GST2 * 4) + kb);
            ldm_x4(a_m[0], st_base + S_AMID_B + a_off + kb);
            ldm_x4(a_m[1], st_base + S_AMID_B + a_off + 16 * (GST2 * 4) + kb);
            uint32_t b_h[4][2], b_m[4][2];
#pragma unroll
            for (int ni = 0; ni < 4; ni++) {
                uint32_t ad = st_base + b_off + ni * 8 * (GST2 * 4) + kb;
                ldm_x2(b_h[ni][0], b_h[ni][1], ad + S_BHI_B);
                ldm_x2(b_m[ni][0], b_m[ni][1], ad + S_BMID_B);
            }
#pragma unroll
            for (int mi = 0; mi < 2; mi++)
#pragma unroll
                for (int ni = 0; ni < 4; ni++)
                    mma_bf16(acc[mi][ni],
                             a_h[mi][0], a_h[mi][1], a_h[mi][2], a_h[mi][3],
                             b_h[ni][0], b_h[ni][1]);
#pragma unroll
            for (int mi = 0; mi < 2; mi++)
#pragma unroll
                for (int ni = 0; ni < 4; ni++)
                    mma_bf16(acc[mi][ni],
                             a_h[mi][0], a_h[mi][1], a_h[mi][2], a_h[mi][3],
                             b_m[ni][0], b_m[ni][1]);
#pragma unroll
            for (int mi = 0; mi < 2; mi++)
#pragma unroll
                for (int ni = 0; ni < 4; ni++)
                    mma_bf16(acc[mi][ni],
                             a_m[mi][0], a_m[mi][1], a_m[mi][2], a_m[mi][3],
                             b_h[ni][0], b_h[ni][1]);
        }
    }

    if (mode == 0) {
#pragma unroll
        for (int mi = 0; mi < 2; mi++)
#pragma unroll
            for (int ni = 0; ni < 4; ni++) {
                int row0 = bm + warp_m + mi * 16 + g;
                int col  = bn + warp_n + ni * 8 + 2 * c;
                *(float2*)(Cp + (size_t)row0 * N + col) =
                    make_float2(acc[mi][ni][0], acc[mi][ni][1]);
                *(float2*)(Cp + (size_t)(row0 + 8) * N + col) =
                    make_float2(acc[mi][ni][2], acc[mi][ni][3]);
            }
    } else {
#pragma unroll
        for (int mi = 0; mi < 2; mi++)
#pragma unroll
            for (int ni = 0; ni < 4; ni++) {
                int colg   = bn + warp_n + ni * 8 + 2 * c;
                int region = colg >> 11;          // 0=q,1=k,2=v
                int h      = (colg & 2047) >> 7;
                int hc     = colg & 127;
                int p      = hc >> 1;
#pragma unroll
                for (int half = 0; half < 2; half++) {
                    int ig = bm + warp_m + mi * 16 + g + half * 8;   // b*SEQ + t
                    int b  = ig >> 11;
                    int t  = ig & 2047;
                    float v0 = acc[mi][ni][2 * half];
                    float v1 = acc[mi][ni][2 * half + 1];
                    if (region < 2) {
                        float re = v0, im = v1;
                        if (h < NHEADS / 2) {
                            float c0 = cosT[t * 64 + p];
                            float s0 = sinT[t * 64 + p];
                            re = v0 * c0 - v1 * s0;
                            im = v0 * s0 + v1 * c0;
                        }
                        uint32_t hi, mid;
                        split2(re, im, hi, mid);
                        size_t idx = (((size_t)b * NHEADS + h) * SEQ + t) * 64 + p;
                        if (region == 0) { Qh[idx] = hi; Qm[idx] = mid; }
                        else             { Kh[idx] = hi; Km[idx] = mid; }
                    } else {
                        float* pv = Vp + (((size_t)b * NHEADS + h) * SEQ + t) * HDIM + hc;
                        *(float2*)pv = make_float2(v0, v1);
                    }
                }
            }
    }
}

// ---------------------------------------------------------------------------
// V transpose + split: g_v[bh][t][d] -> vt[bh][d][t/2] packed bf16 pairs.
// ---------------------------------------------------------------------------
__global__ __launch_bounds__(256)
void vt_split_kernel(const float* __restrict__ v,
                     uint32_t* __restrict__ vthi, uint32_t* __restrict__ vtmid)
{
    __shared__ float tile[64 * 129];
    const int bhh   = blockIdx.x;
    const int chunk = blockIdx.y;
    const int tid   = threadIdx.x;

    const float* vb = v + ((size_t)bhh * SEQ + chunk * 64) * HDIM;
#pragma unroll
    for (int l = 0; l < 8; l++) {
        int slot = tid + l * 256;
        int row  = slot >> 5;
        int c4   = (slot & 31) << 2;
        float4 val = *(const float4*)(vb + row * HDIM + c4);
        tile[row * 129 + c4 + 0] = val.x;
        tile[row * 129 + c4 + 1] = val.y;
        tile[row * 129 + c4 + 2] = val.z;
        tile[row * 129 + c4 + 3] = val.w;
    }
    __syncthreads();
#pragma unroll
    for (int l = 0; l < 16; l++) {
        int slot = tid + l * 256;
        int d  = slot >> 5;
        int sp = slot & 31;
        float f0 = tile[(2 * sp)     * 129 + d];
        float f1 = tile[(2 * sp + 1) * 129 + d];
        uint32_t hi, mid;
        split2(f0, f1, hi, mid);
        size_t idx = ((size_t)bhh * 128 + d) * (SEQ / 2) + chunk * 32 + sp;
        vthi[idx]  = hi;
        vtmid[idx] = mid;
    }
}

// ---------------------------------------------------------------------------
// Flash attention: packed inputs, cp.async double buffer, ldmatrix, bf16 x3,
// non-volatile MMA asm (ptxas schedules).
// ---------------------------------------------------------------------------
#define QK2A 68
#define VT2A 36
#define PSP  36                // packed Ps row stride (u32)
#define OFF_QHI   0
#define OFF_QMID  4352
#define OFF_KST   8704         // + st*8704 ; hi +0, mid +4352
#define K_ST_SZ   8704
#define OFF_VST   26112        // + st*9216 ; hi +0, mid +4608
#define V_ST_SZ   9216
#define OFF_PSH   44544
#define OFF_PSM   46848
#define OFF_PMAX  49152        // 128 floats
#define OFF_LP    49280        // 128 floats
#define ATT_SMEM_U32 49408     // 197632 bytes

__global__ __launch_bounds__(256, 1)
void attn_tc_kernel(const uint32_t* __restrict__ qhiG, const uint32_t* __restrict__ qmidG,
                    const uint32_t* __restrict__ khiG, const uint32_t* __restrict__ kmidG,
                    const uint32_t* __restrict__ vthiG, const uint32_t* __restrict__ vtmidG,
                    uint32_t* __restrict__ outHi, uint32_t* __restrict__ outMid)
{
    extern __shared__ uint32_t smu[];
    const uint32_t smem_base = (uint32_t)__cvta_generic_to_shared(smu);
    float* pmax = (float*)(smu + OFF_PMAX);
    float* l_p  = (float*)(smu + OFF_LP);

    const int tid  = threadIdx.x;
    const int lane = tid & 31;
    const int wid  = tid >> 5;
    const int g    = lane >> 2;
    const int c    = lane & 3;
    const int wm   = wid & 3;
    const int wn   = wid >> 2;

    const int bh = blockIdx.y;
    const int qt = (int)gridDim.x - 1 - (int)blockIdx.x;   // heavy tiles first
    const int h  = bh & (NHEADS - 1);
    const int b  = bh >> 4;

    const float scale = 0.08838834764831845f;   // 1/sqrt(128)
    const int row0 = wm * 16 + g;
    const int row1 = row0 + 8;

    // --- load Q tile (packed) ---
    {
        const uint32_t* qh = qhiG  + ((size_t)bh * SEQ + qt * 64) * 64;
        const uint32_t* qm = qmidG + ((size_t)bh * SEQ + qt * 64) * 64;
#pragma unroll
        for (int l = 0; l < 4; l++) {
            int slot = tid + l * 256;
            int row  = slot >> 4;
            int q4   = (slot & 15) << 2;
            *(uint4*)(smu + OFF_QHI  + row * QK2A + q4) = *(const uint4*)(qh + row * 64 + q4);
            *(uint4*)(smu + OFF_QMID + row * QK2A + q4) = *(const uint4*)(qm + row * 64 + q4);
        }
    }

    auto load_kv = [&](int j, int st) {
        const uint32_t* kh = khiG  + ((size_t)bh * SEQ + j * 64) * 64;
        const uint32_t* km = kmidG + ((size_t)bh * SEQ + j * 64) * 64;
        uint32_t* kd = smu + OFF_KST + st * K_ST_SZ;
#pragma unroll
        for (int l = 0; l < 4; l++) {
            int slot = tid + l * 256;
            int row  = slot >> 4;
            int q4   = (slot & 15) << 2;
            cp_async16(kd + row * QK2A + q4,        kh + row * 64 + q4);
            cp_async16(kd + 4352 + row * QK2A + q4, km + row * 64 + q4);
        }
        const uint32_t* vh = vthiG  + (size_t)bh * 128 * (SEQ / 2);
        const uint32_t* vm = vtmidG + (size_t)bh * 128 * (SEQ / 2);
        uint32_t* vd = smu + OFF_VST + st * V_ST_SZ;
#pragma unroll
        for (int l = 0; l < 4; l++) {
            int slot = tid + l * 256;
            int d  = slot >> 3;
            int q4 = (slot & 7) << 2;
            cp_async16(vd + d * VT2A + q4,        vh + (size_t)d * (SEQ / 2) + j * 32 + q4);
            cp_async16(vd + 4608 + d * VT2A + q4, vm + (size_t)d * (SEQ / 2) + j * 32 + q4);
        }
    };

    float o[8][4];
#pragma unroll
    for (int ni = 0; ni < 8; ni++)
#pragma unroll
        for (int e = 0; e < 4; e++) o[ni][e] = 0.0f;
    float m0r = -1e30f, m1r = -1e30f;
    float l0r = 0.0f,   l1r = 0.0f;

    // ldmatrix lane offsets (bytes)
    const uint32_t qa_off = (uint32_t)(wm * 16 + (lane & 15)) * (QK2A * 4) + ((lane >> 4) << 4);
    const uint32_t kb_off = (uint32_t)(wn * 32 + (lane & 7)) * (QK2A * 4) + (((lane >> 3) & 1) << 4);
    const uint32_t vb_off = (uint32_t)(wn * 64 + (lane & 7)) * (VT2A * 4) + (((lane >> 3) & 1) << 4);
    const uint32_t pa_off = (uint32_t)(wm * 16 + (lane & 15)) * (PSP * 4) + ((lane >> 4) << 4);

    load_kv(0, 0);
    cp_commit();

    for (int j = 0; j <= qt; j++) {
        const int st = j & 1;
        if (j < qt) {
            load_kv(j + 1, st ^ 1);
            cp_commit();
            cp_wait<1>();
        } else {
            cp_wait<0>();
        }
        __syncthreads();                      // (1) tiles ready

        // --- S = Q K^T ---
        float s[4][4];
#pragma unroll
        for (int ni = 0; ni < 4; ni++)
#pragma unroll
            for (int e = 0; e < 4; e++) s[ni][e] = 0.0f;

        const uint32_t kstb = smem_base + (OFF_KST + st * K_ST_SZ) * 4;
#pragma unroll
        for (int kk2 = 0; kk2 < 64; kk2 += 8) {
            const uint32_t kb = kk2 * 4;
            uint32_t ah[4], am[4];
            ldm_x4(ah, smem_base + OFF_QHI * 4 + qa_off + kb);
            ldm_x4(am, smem_base + OFF_QMID * 4 + qa_off + kb);
            uint32_t bh_[4][2], bm_[4][2];
#pragma unroll
            for (int ni = 0; ni < 4; ni++) {
                uint32_t ad = kstb + kb_off + ni * 8 * (QK2A * 4) + kb;
                ldm_x2(bh_[ni][0], bh_[ni][1], ad);
                ldm_x2(bm_[ni][0], bm_[ni][1], ad + 4352 * 4);
            }
#pragma unroll
            for (int ni = 0; ni < 4; ni++)
                mma_bf16(s[ni], ah[0], ah[1], ah[2], ah[3], bh_[ni][0], bh_[ni][1]);
#pragma unroll
            for (int ni = 0; ni < 4; ni++)
                mma_bf16(s[ni], ah[0], ah[1], ah[2], ah[3], bm_[ni][0], bm_[ni][1]);
#pragma unroll
            for (int ni = 0; ni < 4; ni++)
                mma_bf16(s[ni], am[0], am[1], am[2], am[3], bh_[ni][0], bh_[ni][1]);
        }

        // --- scale + causal mask ---
        const bool diag = (j == qt);
#pragma unroll
        for (int ni = 0; ni < 4; ni++) {
            int colb = wn * 32 + ni * 8 + 2 * c;
#pragma unroll
            for (int e = 0; e < 4; e++) {
                int col = colb + (e & 1);
                int row = (e < 2) ? row0 : row1;
                float val = s[ni][e] * scale;
                if (diag && col > row) val = -1e30f;
                s[ni][e] = val;
            }
        }

        // --- partial row max over this warp's 32 cols ---
        float mx0 = -1e30f, mx1 = -1e30f;
#pragma unroll
        for (int ni = 0; ni < 4; ni++) {
            mx0 = fmaxf(mx0, fmaxf(s[ni][0], s[ni][1]));
            mx1 = fmaxf(mx1, fmaxf(s[ni][2], s[ni][3]));
        }
#pragma unroll
        for (int off = 1; off < 4; off <<= 1) {
            mx0 = fmaxf(mx0, __shfl_xor_sync(0xffffffffu, mx0, off));
            mx1 = fmaxf(mx1, __shfl_xor_sync(0xffffffffu, mx1, off));
        }
        if (c == 0) {
            pmax[row0 * 2 + wn] = mx0;
            pmax[row1 * 2 + wn] = mx1;
        }
        __syncthreads();                      // (2) pmax visible

        // --- per-thread redundant m update ---
        float mn0 = fmaxf(m0r, fmaxf(pmax[row0 * 2], pmax[row0 * 2 + 1]));
        float mn1 = fmaxf(m1r, fmaxf(pmax[row1 * 2], pmax[row1 * 2 + 1]));
        float a0 = __expf(m0r - mn0);
        float a1 = __expf(m1r - mn1);
        m0r = mn0; m1r = mn1;

        // --- exp, packed P store, local l partials; alpha-rescale O ---
        float rs0 = 0.0f, rs1 = 0.0f;
#pragma unroll
        for (int ni = 0; ni < 4; ni++) {
            int pair = wn * 16 + ni * 4 + c;
            float p0 = __expf(s[ni][0] - mn0);
            float p1 = __expf(s[ni][1] - mn0);
            float p2 = __expf(s[ni][2] - mn1);
            float p3 = __expf(s[ni][3] - mn1);
            rs0 += p0 + p1; rs1 += p2 + p3;
            uint32_t hi, mid;
            split2(p0, p1, hi, mid);
            smu[OFF_PSH + row0 * PSP + pair] = hi;
            smu[OFF_PSM + row0 * PSP + pair] = mid;
            split2(p2, p3, hi, mid);
            smu[OFF_PSH + row1 * PSP + pair] = hi;
            smu[OFF_PSM + row1 * PSP + pair] = mid;
        }
        l0r = l0r * a0 + rs0;
        l1r = l1r * a1 + rs1;
#pragma unroll
        for (int ni = 0; ni < 8; ni++) {
            o[ni][0] *= a0; o[ni][1] *= a0;
            o[ni][2] *= a1; o[ni][3] *= a1;
        }
        __syncthreads();                      // (3) P visible

        // --- O += P V ---
        const uint32_t vstb = smem_base + (OFF_VST + st * V_ST_SZ) * 4;
#pragma unroll
        for (int kks = 0; kks < 64; kks += 16) {
            uint32_t ph[4], pm_[4];
            ldm_x4(ph,  smem_base + OFF_PSH * 4 + pa_off + kks * 2);
            ldm_x4(pm_, smem_base + OFF_PSM * 4 + pa_off + kks * 2);
            const uint32_t kb = (kks >> 1) * 4;
            uint32_t vh_[8][2], vm_[8][2];
#pragma unroll
            for (int ni = 0; ni < 8; ni++) {
                uint32_t ad = vstb + vb_off + ni * 8 * (VT2A * 4) + kb;
                ldm_x2(vh_[ni][0], vh_[ni][1], ad);
                ldm_x2(vm_[ni][0], vm_[ni][1], ad + 4608 * 4);
            }
#pragma unroll
            for (int ni = 0; ni < 8; ni++)
                mma_bf16(o[ni], ph[0], ph[1], ph[2], ph[3], vh_[ni][0], vh_[ni][1]);
#pragma unroll
            for (int ni = 0; ni < 8; ni++)
                mma_bf16(o[ni], ph[0], ph[1], ph[2], ph[3], vm_[ni][0], vm_[ni][1]);
#pragma unroll
            for (int ni = 0; ni < 8; ni++)
                mma_bf16(o[ni], pm_[0], pm_[1], pm_[2], pm_[3], vh_[ni][0], vh_[ni][1]);
        }
        __syncthreads();                      // (4) stage/Ps reuse safe
    }

    // --- l reduction: quad shuffle then cross-warp via smem ---
#pragma unroll
    for (int off = 1; off < 4; off <<= 1) {
        l0r += __shfl_xor_sync(0xffffffffu, l0r, off);
        l1r += __shfl_xor_sync(0xffffffffu, l1r, off);
    }
    if (c == 0) {
        l_p[row0 * 2 + wn] = l0r;
        l_p[row1 * 2 + wn] = l1r;
    }
    __syncthreads();
    float il0 = 1.0f / (l_p[row0 * 2] + l_p[row0 * 2 + 1]);
    float il1 = 1.0f / (l_p[row1 * 2] + l_p[row1 * 2 + 1]);

    size_t grow0 = (size_t)b * SEQ + qt * 64 + row0;
    size_t grow1 = (size_t)b * SEQ + qt * 64 + row1;
#pragma unroll
    for (int ni = 0; ni < 8; ni++) {
        int col  = wn * 64 + ni * 8 + 2 * c;
        int pidx = h * 64 + (col >> 1);
        uint32_t hi, mid;
        split2(o[ni][0] * il0, o[ni][1] * il0, hi, mid);
        outHi [grow0 * (DMODEL / 2) + pidx] = hi;
        outMid[grow0 * (DMODEL / 2) + pidx] = mid;
        split2(o[ni][2] * il1, o[ni][3] * il1, hi, mid);
        outHi [grow1 * (DMODEL / 2) + pidx] = hi;
        outMid[grow1 * (DMODEL / 2) + pidx] = mid;
    }
}

// ---------------------------------------------------------------------------
extern "C" void kernel_launch(void* const* d_in, const int* in_sizes, int n_in,
                              void* d_out, int out_size)
{
    const float* x    = (const float*)d_in[0];   // [2,2048,2048]
    const float* Wqkv = (const float*)d_in[1];   // [6144,2048]
    const float* Wout = (const float*)d_in[2];   // [2048,2048]
    const float* cosT = (const float*)d_in[3];   // [2048,64]
    const float* sinT = (const float*)d_in[4];   // [2048,64]
    float* out = (float*)d_out;                  // [2,2048,2048]
    (void)in_sizes; (void)n_in; (void)out_size;

    float* gv;
    uint32_t *ahi, *amid, *bhi, *bmid, *whi, *wmid;
    uint32_t *qhi, *qmid, *khi, *kmid, *vthi, *vtmid;
    cudaGetSymbolAddress((void**)&gv,    g_v);
    cudaGetSymbolAddress((void**)&ahi,   g_ahi);
    cudaGetSymbolAddress((void**)&amid,  g_amid);
    cudaGetSymbolAddress((void**)&bhi,   g_bhi);
    cudaGetSymbolAddress((void**)&bmid,  g_bmid);
    cudaGetSymbolAddress((void**)&whi,   g_whi);
    cudaGetSymbolAddress((void**)&wmid,  g_wmid);
    cudaGetSymbolAddress((void**)&qhi,   g_qhi);
    cudaGetSymbolAddress((void**)&qmid,  g_qmid);
    cudaGetSymbolAddress((void**)&khi,   g_khi);
    cudaGetSymbolAddress((void**)&kmid,  g_kmid);
    cudaGetSymbolAddress((void**)&vthi,  g_vthi);
    cudaGetSymbolAddress((void**)&vtmid, g_vtmid);

    const int attn_smem = ATT_SMEM_U32 * (int)sizeof(uint32_t);   // 197632
    cudaFuncSetAttribute(gemm_nt_tc_kernel,
                         cudaFuncAttributeMaxDynamicSharedMemorySize, GEMM_SMEM_BYTES);
    cudaFuncSetAttribute(attn_tc_kernel,
                         cudaFuncAttributeMaxDynamicSharedMemorySize, attn_smem);

    // 1-3) splits first so ncu (-s 5) profiles the QKV GEMM next
    split_kernel<<<(BT * DMODEL / 4 + 255) / 256, 256>>>(x, ahi, amid, BT * DMODEL / 4);
    split_kernel<<<(3 * DMODEL * DMODEL / 4 + 255) / 256, 256>>>(Wqkv, bhi, bmid,
                                                                 3 * DMODEL * DMODEL / 4);
    split_kernel<<<(DMODEL * DMODEL / 4 + 255) / 256, 256>>>(Wout, whi, wmid,
                                                             DMODEL * DMODEL / 4);

    // 4) QKV projection
    gemm_nt_tc_kernel<<<dim3(48, 32), 512, GEMM_SMEM_BYTES>>>(
        ahi, amid, bhi, bmid, cosT, sinT,
        qhi, qmid, khi, kmid, gv, nullptr, BT, 3 * DMODEL, DMODEL, 1);

    // 5) V transpose + split into packed Vt
    vt_split_kernel<<<dim3(BATCH * NHEADS, SEQ / 64), 256>>>(gv, vthi, vtmid);

    // 6) Causal flash attention
    attn_tc_kernel<<<dim3(SEQ / 64, BATCH * NHEADS), 256, attn_smem>>>(
        qhi, qmid, khi, kmid, vthi, vtmid, ahi, amid);

    // 7) Output projection into d_out
    gemm_nt_tc_kernel<<<dim3(16, 32), 512, GEMM_SMEM_BYTES>>>(
        ahi, amid, whi, wmid, nullptr, nullptr,
        nullptr, nullptr, nullptr, nullptr, nullptr, out, BT, DMODEL, DMODEL, 0);
}

// round 17
// speedup vs baseline: 1.9254x; 1.3698x over previous
#include <cuda_runtime.h>
#include <cuda_fp16.h>
#include <cstdint>
#include <cstddef>

#define BATCH   2
#define SEQ     2048
#define DMODEL  2048
#define NHEADS  16
#define HDIM    128
#define BT      (BATCH * SEQ)   // 4096

// Scratch (device globals — allocation-free per harness rules).
static __device__ float    g_v[(size_t)BATCH * NHEADS * SEQ * HDIM];
// packed fp16 (2 per u32)
static __device__ uint32_t g_ahi [(size_t)BT * DMODEL / 2];       // A hi
static __device__ uint32_t g_amid[(size_t)BT * DMODEL / 2];       // A mid
static __device__ uint32_t g_b   [(size_t)3 * DMODEL * DMODEL / 2];  // Wqkv single
static __device__ uint32_t g_w   [(size_t)DMODEL * DMODEL / 2];      // Wout single
static __device__ uint32_t g_qhi [(size_t)BATCH * NHEADS * SEQ * (HDIM / 2)];
static __device__ uint32_t g_qmid[(size_t)BATCH * NHEADS * SEQ * (HDIM / 2)];
static __device__ uint32_t g_k   [(size_t)BATCH * NHEADS * SEQ * (HDIM / 2)];  // single
static __device__ uint32_t g_vt  [(size_t)BATCH * NHEADS * HDIM * (SEQ / 2)];  // single

// ---------------------------------------------------------------------------
// fp16 helpers.  pack_f16(f_lo, f_hi): f_lo -> low 16 bits.
// ---------------------------------------------------------------------------
__device__ __forceinline__ uint32_t pack_f16(float f_lo, float f_hi) {
    uint32_t r;
    asm("cvt.rn.f16x2.f32 %0, %1, %2;" : "=r"(r) : "f"(f_hi), "f"(f_lo));
    return r;
}
__device__ __forceinline__ float2 unpack_f16(uint32_t u) {
    __half2 h = *reinterpret_cast<__half2*>(&u);
    return make_float2(__low2float(h), __high2float(h));
}
__device__ __forceinline__ void split2h(float f0, float f1, uint32_t& hi, uint32_t& mid) {
    hi = pack_f16(f0, f1);
    float2 hf = unpack_f16(hi);
    mid = pack_f16(f0 - hf.x, f1 - hf.y);
}

// Non-volatile pure-register fp16 MMA (ptxas schedules freely).
__device__ __forceinline__ void mma_f16(float d[4],
                                        uint32_t a0, uint32_t a1, uint32_t a2, uint32_t a3,
                                        uint32_t b0, uint32_t b1) {
    asm("mma.sync.aligned.m16n8k16.row.col.f32.f16.f16.f32 "
        "{%0,%1,%2,%3}, {%4,%5,%6,%7}, {%8,%9}, {%0,%1,%2,%3};"
        : "+f"(d[0]), "+f"(d[1]), "+f"(d[2]), "+f"(d[3])
        : "r"(a0), "r"(a1), "r"(a2), "r"(a3), "r"(b0), "r"(b1));
}

__device__ __forceinline__ void ldm_x4(uint32_t a[4], uint32_t addr) {
    asm("ldmatrix.sync.aligned.m8n8.x4.shared.b16 {%0,%1,%2,%3}, [%4];"
        : "=r"(a[0]), "=r"(a[1]), "=r"(a[2]), "=r"(a[3]) : "r"(addr) : "memory");
}
__device__ __forceinline__ void ldm_x2(uint32_t& b0, uint32_t& b1, uint32_t addr) {
    asm("ldmatrix.sync.aligned.m8n8.x2.shared.b16 {%0,%1}, [%2];"
        : "=r"(b0), "=r"(b1) : "r"(addr) : "memory");
}

__device__ __forceinline__ void cp_async16(void* smem_dst, const void* gmem_src) {
    uint32_t s = (uint32_t)__cvta_generic_to_shared(smem_dst);
    asm volatile("cp.async.cg.shared.global [%0], [%1], 16;"
                 :: "r"(s), "l"(gmem_src) : "memory");
}
__device__ __forceinline__ void cp_commit() {
    asm volatile("cp.async.commit_group;" ::: "memory");
}
template <int N>
__device__ __forceinline__ void cp_wait() {
    asm volatile("cp.async.wait_group %0;" :: "n"(N) : "memory");
}

// ---------------------------------------------------------------------------
// A-side split kernel: float -> packed fp16 (hi, mid).
// ---------------------------------------------------------------------------
__global__ void split_kernel(const float* __restrict__ in,
                             uint32_t* __restrict__ hi, uint32_t* __restrict__ mid,
                             int n4)
{
    int i = blockIdx.x * blockDim.x + threadIdx.x;
    if (i >= n4) return;
    float4 v = ((const float4*)in)[i];
    uint32_t h0, m0, h1, m1;
    split2h(v.x, v.y, h0, m0);
    split2h(v.z, v.w, h1, m1);
    ((uint2*)hi)[i]  = make_uint2(h0, h1);
    ((uint2*)mid)[i] = make_uint2(m0, m1);
}

// B-side convert kernel: float -> packed fp16 single.
__global__ void cvt_kernel(const float* __restrict__ in,
                           uint32_t* __restrict__ outp, int n4)
{
    int i = blockIdx.x * blockDim.x + threadIdx.x;
    if (i >= n4) return;
    float4 v = ((const float4*)in)[i];
    ((uint2*)outp)[i] = make_uint2(pack_f16(v.x, v.y), pack_f16(v.z, v.w));
}

// ---------------------------------------------------------------------------
// NT GEMM, fp16 2-term (A split, B single), ldmatrix + cp.async 3-stage ring.
// C[M,N] = A[M,K] * B[N,K]^T. 128x128 block, BK=64 floats (32 u32),
// 512 threads = 16 warps (4m x 4n), warp tile 32x32.
// mode 0: plain fp32 store.  mode 1: QKV epilogue (RoPE; q split, k single,
// v fp32 scatter).
// ---------------------------------------------------------------------------
#define GST2 36
#define G_ARR2 (128 * GST2)          // 4608 u32
#define SF_AHI_B  0
#define SF_AMID_B (G_ARR2 * 4)
#define SF_B_B    (2 * G_ARR2 * 4)
#define F_STAGE   (3 * G_ARR2)       // 13824 u32 = 55296 B
#define GEMM_SMEM_BYTES (3 * F_STAGE * 4)   // 165888

__global__ __launch_bounds__(512, 1)
void gemm_nt_tc_kernel(const uint32_t* __restrict__ Ahi, const uint32_t* __restrict__ Amid,
                       const uint32_t* __restrict__ Bs,
                       const float* __restrict__ cosT, const float* __restrict__ sinT,
                       uint32_t* __restrict__ Qh, uint32_t* __restrict__ Qm,
                       uint32_t* __restrict__ Kp,
                       float* __restrict__ Vp, float* __restrict__ Cp,
                       int M, int N, int K, int mode)
{
    extern __shared__ uint32_t gsm[];
    const uint32_t smem_base = (uint32_t)__cvta_generic_to_shared(gsm);

    const int tid  = threadIdx.x;
    const int lane = tid & 31;
    const int wid  = tid >> 5;
    const int g    = lane >> 2;
    const int c    = lane & 3;
    const int warp_m = (wid & 3) * 32;
    const int warp_n = (wid >> 2) * 32;

    const int bm = blockIdx.y * 128;
    const int bn = blockIdx.x * 128;
    const int Ku = K >> 1;

    const uint32_t* AhiB  = Ahi  + (size_t)bm * Ku;
    const uint32_t* AmidB = Amid + (size_t)bm * Ku;
    const uint32_t* BB    = Bs   + (size_t)bn * Ku;

    float acc[2][4][4];
#pragma unroll
    for (int mi = 0; mi < 2; mi++)
#pragma unroll
        for (int ni = 0; ni < 4; ni++)
#pragma unroll
            for (int e = 0; e < 4; e++) acc[mi][ni][e] = 0.0f;

    const int KT = K >> 6;

    auto load_stage = [&](int kt, int st) {
        char* dst = (char*)gsm + (size_t)st * (F_STAGE * 4);
        int ko = kt << 5;
#pragma unroll
        for (int l = 0; l < 2; l++) {
            int idx = tid + l * 512;
            int row = idx >> 3;
            int c4  = (idx & 7) << 2;
            size_t go = (size_t)row * Ku + ko + c4;
            uint32_t so = row * (GST2 * 4) + c4 * 4;
            cp_async16(dst + SF_AHI_B  + so, AhiB  + go);
            cp_async16(dst + SF_AMID_B + so, AmidB + go);
            cp_async16(dst + SF_B_B    + so, BB    + go);
        }
    };

    // ldmatrix lane offsets (bytes)
    const uint32_t a_off = (uint32_t)(warp_m + (lane & 15)) * (GST2 * 4) + ((lane >> 4) << 4);
    const uint32_t b_off = (uint32_t)(warp_n + (lane & 7)) * (GST2 * 4) + (((lane >> 3) & 1) << 4);

    load_stage(0, 0);
    cp_commit();
    if (KT > 1) { load_stage(1, 1); cp_commit(); }

    for (int kt = 0; kt < KT; kt++) {
        if (kt + 1 < KT) {
            cp_wait<1>();
        } else {
            cp_wait<0>();
        }
        __syncthreads();

        if (kt + 2 < KT) {
            load_stage(kt + 2, (kt + 2) % 3);
            cp_commit();
        }

        const uint32_t st_base = smem_base + (uint32_t)(kt % 3) * (F_STAGE * 4);

#pragma unroll
        for (int kk2 = 0; kk2 < 32; kk2 += 8) {
            const uint32_t kb = kk2 * 4;
            uint32_t a_h[2][4], a_m[2][4];
            ldm_x4(a_h[0], st_base + SF_AHI_B  + a_off + kb);
            ldm_x4(a_h[1], st_base + SF_AHI_B  + a_off + 16 * (GST2 * 4) + kb);
            ldm_x4(a_m[0], st_base + SF_AMID_B + a_off + kb);
            ldm_x4(a_m[1], st_base + SF_AMID_B + a_off + 16 * (GST2 * 4) + kb);
            uint32_t b_[4][2];
#pragma unroll
            for (int ni = 0; ni < 4; ni++) {
                uint32_t ad = st_base + SF_B_B + b_off + ni * 8 * (GST2 * 4) + kb;
                ldm_x2(b_[ni][0], b_[ni][1], ad);
            }
#pragma unroll
            for (int mi = 0; mi < 2; mi++)
#pragma unroll
                for (int ni = 0; ni < 4; ni++)
                    mma_f16(acc[mi][ni],
                            a_h[mi][0], a_h[mi][1], a_h[mi][2], a_h[mi][3],
                            b_[ni][0], b_[ni][1]);
#pragma unroll
            for (int mi = 0; mi < 2; mi++)
#pragma unroll
                for (int ni = 0; ni < 4; ni++)
                    mma_f16(acc[mi][ni],
                            a_m[mi][0], a_m[mi][1], a_m[mi][2], a_m[mi][3],
                            b_[ni][0], b_[ni][1]);
        }
    }

    if (mode == 0) {
#pragma unroll
        for (int mi = 0; mi < 2; mi++)
#pragma unroll
            for (int ni = 0; ni < 4; ni++) {
                int row0 = bm + warp_m + mi * 16 + g;
                int col  = bn + warp_n + ni * 8 + 2 * c;
                *(float2*)(Cp + (size_t)row0 * N + col) =
                    make_float2(acc[mi][ni][0], acc[mi][ni][1]);
                *(float2*)(Cp + (size_t)(row0 + 8) * N + col) =
                    make_float2(acc[mi][ni][2], acc[mi][ni][3]);
            }
    } else {
#pragma unroll
        for (int mi = 0; mi < 2; mi++)
#pragma unroll
            for (int ni = 0; ni < 4; ni++) {
                int colg   = bn + warp_n + ni * 8 + 2 * c;
                int region = colg >> 11;          // 0=q,1=k,2=v
                int h      = (colg & 2047) >> 7;
                int hc     = colg & 127;
                int p      = hc >> 1;
#pragma unroll
                for (int half = 0; half < 2; half++) {
                    int ig = bm + warp_m + mi * 16 + g + half * 8;   // b*SEQ + t
                    int b  = ig >> 11;
                    int t  = ig & 2047;
                    float v0 = acc[mi][ni][2 * half];
                    float v1 = acc[mi][ni][2 * half + 1];
                    if (region < 2) {
                        float re = v0, im = v1;
                        if (h < NHEADS / 2) {
                            float c0 = cosT[t * 64 + p];
                            float s0 = sinT[t * 64 + p];
                            re = v0 * c0 - v1 * s0;
                            im = v0 * s0 + v1 * c0;
                        }
                        size_t idx = (((size_t)b * NHEADS + h) * SEQ + t) * 64 + p;
                        if (region == 0) {
                            uint32_t hi, mid;
                            split2h(re, im, hi, mid);
                            Qh[idx] = hi; Qm[idx] = mid;
                        } else {
                            Kp[idx] = pack_f16(re, im);
                        }
                    } else {
                        float* pv = Vp + (((size_t)b * NHEADS + h) * SEQ + t) * HDIM + hc;
                        *(float2*)pv = make_float2(v0, v1);
                    }
                }
            }
    }
}

// ---------------------------------------------------------------------------
// V transpose: g_v[bh][t][d] -> vt[bh][d][t/2] packed fp16 single.
// ---------------------------------------------------------------------------
__global__ __launch_bounds__(256)
void vt_split_kernel(const float* __restrict__ v, uint32_t* __restrict__ vt)
{
    __shared__ float tile[64 * 129];
    const int bhh   = blockIdx.x;
    const int chunk = blockIdx.y;
    const int tid   = threadIdx.x;

    const float* vb = v + ((size_t)bhh * SEQ + chunk * 64) * HDIM;
#pragma unroll
    for (int l = 0; l < 8; l++) {
        int slot = tid + l * 256;
        int row  = slot >> 5;
        int c4   = (slot & 31) << 2;
        float4 val = *(const float4*)(vb + row * HDIM + c4);
        tile[row * 129 + c4 + 0] = val.x;
        tile[row * 129 + c4 + 1] = val.y;
        tile[row * 129 + c4 + 2] = val.z;
        tile[row * 129 + c4 + 3] = val.w;
    }
    __syncthreads();
#pragma unroll
    for (int l = 0; l < 16; l++) {
        int slot = tid + l * 256;
        int d  = slot >> 5;
        int sp = slot & 31;
        float f0 = tile[(2 * sp)     * 129 + d];
        float f1 = tile[(2 * sp + 1) * 129 + d];
        size_t idx = ((size_t)bhh * 128 + d) * (SEQ / 2) + chunk * 32 + sp;
        vt[idx] = pack_f16(f0, f1);
    }
}

// ---------------------------------------------------------------------------
// Flash attention: fp16 2-term (Q and P split; K and V single).
// cp.async double buffer, ldmatrix. 256 threads = 8 warps: wm=wid&3, wn=wid>>2.
// ---------------------------------------------------------------------------
#define QK2A 68
#define VT2A 36
#define PSP  36
#define OFF_QHI   0            // 4352
#define OFF_QMID  4352         // 4352
#define OFF_KST   8704         // + st*4352 (single)
#define K_ST      4352
#define OFF_VST   17408        // + st*4608 (single)
#define V_ST      4608
#define OFF_PSH   26624        // 2304
#define OFF_PSM   28928        // 2304
#define OFF_PMAX  31232        // 128 floats
#define OFF_LP    31360        // 128 floats
#define ATT_SMEM_U32 31488     // 125952 bytes

__global__ __launch_bounds__(256, 1)
void attn_tc_kernel(const uint32_t* __restrict__ qhiG, const uint32_t* __restrict__ qmidG,
                    const uint32_t* __restrict__ kG, const uint32_t* __restrict__ vtG,
                    uint32_t* __restrict__ outHi, uint32_t* __restrict__ outMid)
{
    extern __shared__ uint32_t smu[];
    const uint32_t smem_base = (uint32_t)__cvta_generic_to_shared(smu);
    float* pmax = (float*)(smu + OFF_PMAX);
    float* l_p  = (float*)(smu + OFF_LP);

    const int tid  = threadIdx.x;
    const int lane = tid & 31;
    const int wid  = tid >> 5;
    const int g    = lane >> 2;
    const int c    = lane & 3;
    const int wm   = wid & 3;
    const int wn   = wid >> 2;

    const int bh = blockIdx.y;
    const int qt = (int)gridDim.x - 1 - (int)blockIdx.x;   // heavy tiles first
    const int h  = bh & (NHEADS - 1);
    const int b  = bh >> 4;

    const float scale = 0.08838834764831845f;   // 1/sqrt(128)
    const int row0 = wm * 16 + g;
    const int row1 = row0 + 8;

    // --- load Q tile (packed hi/mid) ---
    {
        const uint32_t* qh = qhiG  + ((size_t)bh * SEQ + qt * 64) * 64;
        const uint32_t* qm = qmidG + ((size_t)bh * SEQ + qt * 64) * 64;
#pragma unroll
        for (int l = 0; l < 4; l++) {
            int slot = tid + l * 256;
            int row  = slot >> 4;
            int q4   = (slot & 15) << 2;
            *(uint4*)(smu + OFF_QHI  + row * QK2A + q4) = *(const uint4*)(qh + row * 64 + q4);
            *(uint4*)(smu + OFF_QMID + row * QK2A + q4) = *(const uint4*)(qm + row * 64 + q4);
        }
    }

    auto load_kv = [&](int j, int st) {
        const uint32_t* kh = kG + ((size_t)bh * SEQ + j * 64) * 64;
        uint32_t* kd = smu + OFF_KST + st * K_ST;
#pragma unroll
        for (int l = 0; l < 4; l++) {
            int slot = tid + l * 256;
            int row  = slot >> 4;
            int q4   = (slot & 15) << 2;
            cp_async16(kd + row * QK2A + q4, kh + row * 64 + q4);
        }
        const uint32_t* vh = vtG + (size_t)bh * 128 * (SEQ / 2);
        uint32_t* vd = smu + OFF_VST + st * V_ST;
#pragma unroll
        for (int l = 0; l < 4; l++) {
            int slot = tid + l * 256;
            int d  = slot >> 3;
            int q4 = (slot & 7) << 2;
            cp_async16(vd + d * VT2A + q4, vh + (size_t)d * (SEQ / 2) + j * 32 + q4);
        }
    };

    float o[8][4];
#pragma unroll
    for (int ni = 0; ni < 8; ni++)
#pragma unroll
        for (int e = 0; e < 4; e++) o[ni][e] = 0.0f;
    float m0r = -1e30f, m1r = -1e30f;
    float l0r = 0.0f,   l1r = 0.0f;

    // ldmatrix lane offsets (bytes)
    const uint32_t qa_off = (uint32_t)(wm * 16 + (lane & 15)) * (QK2A * 4) + ((lane >> 4) << 4);
    const uint32_t kb_off = (uint32_t)(wn * 32 + (lane & 7)) * (QK2A * 4) + (((lane >> 3) & 1) << 4);
    const uint32_t vb_off = (uint32_t)(wn * 64 + (lane & 7)) * (VT2A * 4) + (((lane >> 3) & 1) << 4);
    const uint32_t pa_off = (uint32_t)(wm * 16 + (lane & 15)) * (PSP * 4) + ((lane >> 4) << 4);

    load_kv(0, 0);
    cp_commit();

    for (int j = 0; j <= qt; j++) {
        const int st = j & 1;
        if (j < qt) {
            load_kv(j + 1, st ^ 1);
            cp_commit();
            cp_wait<1>();
        } else {
            cp_wait<0>();
        }
        __syncthreads();                      // (1) tiles ready

        // --- S = Q K^T (2-term) ---
        float s[4][4];
#pragma unroll
        for (int ni = 0; ni < 4; ni++)
#pragma unroll
            for (int e = 0; e < 4; e++) s[ni][e] = 0.0f;

        const uint32_t kstb = smem_base + (OFF_KST + st * K_ST) * 4;
#pragma unroll
        for (int kk2 = 0; kk2 < 64; kk2 += 8) {
            const uint32_t kb = kk2 * 4;
            uint32_t ah[4], am[4];
            ldm_x4(ah, smem_base + OFF_QHI * 4 + qa_off + kb);
            ldm_x4(am, smem_base + OFF_QMID * 4 + qa_off + kb);
            uint32_t bh_[4][2];
#pragma unroll
            for (int ni = 0; ni < 4; ni++) {
                uint32_t ad = kstb + kb_off + ni * 8 * (QK2A * 4) + kb;
                ldm_x2(bh_[ni][0], bh_[ni][1], ad);
            }
#pragma unroll
            for (int ni = 0; ni < 4; ni++)
                mma_f16(s[ni], ah[0], ah[1], ah[2], ah[3], bh_[ni][0], bh_[ni][1]);
#pragma unroll
            for (int ni = 0; ni < 4; ni++)
                mma_f16(s[ni], am[0], am[1], am[2], am[3], bh_[ni][0], bh_[ni][1]);
        }

        // --- scale + causal mask ---
        const bool diag = (j == qt);
#pragma unroll
        for (int ni = 0; ni < 4; ni++) {
            int colb = wn * 32 + ni * 8 + 2 * c;
#pragma unroll
            for (int e = 0; e < 4; e++) {
                int col = colb + (e & 1);
                int row = (e < 2) ? row0 : row1;
                float val = s[ni][e] * scale;
                if (diag && col > row) val = -1e30f;
                s[ni][e] = val;
            }
        }

        // --- partial row max over this warp's 32 cols ---
        float mx0 = -1e30f, mx1 = -1e30f;
#pragma unroll
        for (int ni = 0; ni < 4; ni++) {
            mx0 = fmaxf(mx0, fmaxf(s[ni][0], s[ni][1]));
            mx1 = fmaxf(mx1, fmaxf(s[ni][2], s[ni][3]));
        }
#pragma unroll
        for (int off = 1; off < 4; off <<= 1) {
            mx0 = fmaxf(mx0, __shfl_xor_sync(0xffffffffu, mx0, off));
            mx1 = fmaxf(mx1, __shfl_xor_sync(0xffffffffu, mx1, off));
        }
        if (c == 0) {
            pmax[row0 * 2 + wn] = mx0;
            pmax[row1 * 2 + wn] = mx1;
        }
        __syncthreads();                      // (2) pmax visible

        // --- per-thread redundant m update ---
        float mn0 = fmaxf(m0r, fmaxf(pmax[row0 * 2], pmax[row0 * 2 + 1]));
        float mn1 = fmaxf(m1r, fmaxf(pmax[row1 * 2], pmax[row1 * 2 + 1]));
        float a0 = __expf(m0r - mn0);
        float a1 = __expf(m1r - mn1);
        m0r = mn0; m1r = mn1;

        // --- exp, packed P store (fp16 hi/mid), l partials; rescale O ---
        float rs0 = 0.0f, rs1 = 0.0f;
#pragma unroll
        for (int ni = 0; ni < 4; ni++) {
            int pair = wn * 16 + ni * 4 + c;
            float p0 = __expf(s[ni][0] - mn0);
            float p1 = __expf(s[ni][1] - mn0);
            float p2 = __expf(s[ni][2] - mn1);
            float p3 = __expf(s[ni][3] - mn1);
            rs0 += p0 + p1; rs1 += p2 + p3;
            uint32_t hi, mid;
            split2h(p0, p1, hi, mid);
            smu[OFF_PSH + row0 * PSP + pair] = hi;
            smu[OFF_PSM + row0 * PSP + pair] = mid;
            split2h(p2, p3, hi, mid);
            smu[OFF_PSH + row1 * PSP + pair] = hi;
            smu[OFF_PSM + row1 * PSP + pair] = mid;
        }
        l0r = l0r * a0 + rs0;
        l1r = l1r * a1 + rs1;
#pragma unroll
        for (int ni = 0; ni < 8; ni++) {
            o[ni][0] *= a0; o[ni][1] *= a0;
            o[ni][2] *= a1; o[ni][3] *= a1;
        }
        __syncthreads();                      // (3) P visible

        // --- O += P V (2-term) ---
        const uint32_t vstb = smem_base + (OFF_VST + st * V_ST) * 4;
#pragma unroll
        for (int kks = 0; kks < 64; kks += 16) {
            uint32_t ph[4], pm_[4];
            ldm_x4(ph,  smem_base + OFF_PSH * 4 + pa_off + kks * 2);
            ldm_x4(pm_, smem_base + OFF_PSM * 4 + pa_off + kks * 2);
            const uint32_t kb = (kks >> 1) * 4;
            uint32_t vh_[8][2];
#pragma unroll
            for (int ni = 0; ni < 8; ni++) {
                uint32_t ad = vstb + vb_off + ni * 8 * (VT2A * 4) + kb;
                ldm_x2(vh_[ni][0], vh_[ni][1], ad);
            }
#pragma unroll
            for (int ni = 0; ni < 8; ni++)
                mma_f16(o[ni], ph[0], ph[1], ph[2], ph[3], vh_[ni][0], vh_[ni][1]);
#pragma unroll
            for (int ni = 0; ni < 8; ni++)
                mma_f16(o[ni], pm_[0], pm_[1], pm_[2], pm_[3], vh_[ni][0], vh_[ni][1]);
        }
        __syncthreads();                      // (4) stage/Ps reuse safe
    }

    // --- l reduction: quad shuffle then cross-warp via smem ---
#pragma unroll
    for (int off = 1; off < 4; off <<= 1) {
        l0r += __shfl_xor_sync(0xffffffffu, l0r, off);
        l1r += __shfl_xor_sync(0xffffffffu, l1r, off);
    }
    if (c == 0) {
        l_p[row0 * 2 + wn] = l0r;
        l_p[row1 * 2 + wn] = l1r;
    }
    __syncthreads();
    float il0 = 1.0f / (l_p[row0 * 2] + l_p[row0 * 2 + 1]);
    float il1 = 1.0f / (l_p[row1 * 2] + l_p[row1 * 2 + 1]);

    size_t grow0 = (size_t)b * SEQ + qt * 64 + row0;
    size_t grow1 = (size_t)b * SEQ + qt * 64 + row1;
#pragma unroll
    for (int ni = 0; ni < 8; ni++) {
        int col  = wn * 64 + ni * 8 + 2 * c;
        int pidx = h * 64 + (col >> 1);
        uint32_t hi, mid;
        split2h(o[ni][0] * il0, o[ni][1] * il0, hi, mid);
        outHi [grow0 * (DMODEL / 2) + pidx] = hi;
        outMid[grow0 * (DMODEL / 2) + pidx] = mid;
        split2h(o[ni][2] * il1, o[ni][3] * il1, hi, mid);
        outHi [grow1 * (DMODEL / 2) + pidx] = hi;
        outMid[grow1 * (DMODEL / 2) + pidx] = mid;
    }
}

// ---------------------------------------------------------------------------
extern "C" void kernel_launch(void* const* d_in, const int* in_sizes, int n_in,
                              void* d_out, int out_size)
{
    const float* x    = (const float*)d_in[0];   // [2,2048,2048]
    const float* Wqkv = (const float*)d_in[1];   // [6144,2048]
    const float* Wout = (const float*)d_in[2];   // [2048,2048]
    const float* cosT = (const float*)d_in[3];   // [2048,64]
    const float* sinT = (const float*)d_in[4];   // [2048,64]
    float* out = (float*)d_out;                  // [2,2048,2048]
    (void)in_sizes; (void)n_in; (void)out_size;

    float* gv;
    uint32_t *ahi, *amid, *gb, *gw, *qhi, *qmid, *gk, *gvt;
    cudaGetSymbolAddress((void**)&gv,   g_v);
    cudaGetSymbolAddress((void**)&ahi,  g_ahi);
    cudaGetSymbolAddress((void**)&amid, g_amid);
    cudaGetSymbolAddress((void**)&gb,   g_b);
    cudaGetSymbolAddress((void**)&gw,   g_w);
    cudaGetSymbolAddress((void**)&qhi,  g_qhi);
    cudaGetSymbolAddress((void**)&qmid, g_qmid);
    cudaGetSymbolAddress((void**)&gk,   g_k);
    cudaGetSymbolAddress((void**)&gvt,  g_vt);

    const int attn_smem = ATT_SMEM_U32 * (int)sizeof(uint32_t);   // 125952
    cudaFuncSetAttribute(gemm_nt_tc_kernel,
                         cudaFuncAttributeMaxDynamicSharedMemorySize, GEMM_SMEM_BYTES);
    cudaFuncSetAttribute(attn_tc_kernel,
                         cudaFuncAttributeMaxDynamicSharedMemorySize, attn_smem);

    // 1-3) conversions first (ncu -s 5 lands on the QKV GEMM)
    split_kernel<<<(BT * DMODEL / 4 + 255) / 256, 256>>>(x, ahi, amid, BT * DMODEL / 4);
    cvt_kernel<<<(3 * DMODEL * DMODEL / 4 + 255) / 256, 256>>>(Wqkv, gb,
                                                               3 * DMODEL * DMODEL / 4);
    cvt_kernel<<<(DMODEL * DMODEL / 4 + 255) / 256, 256>>>(Wout, gw,
                                                           DMODEL * DMODEL / 4);

    // 4) QKV projection
    gemm_nt_tc_kernel<<<dim3(48, 32), 512, GEMM_SMEM_BYTES>>>(
        ahi, amid, gb, cosT, sinT,
        qhi, qmid, gk, gv, nullptr, BT, 3 * DMODEL, DMODEL, 1);

    // 5) V transpose into packed single-fp16 Vt
    vt_split_kernel<<<dim3(BATCH * NHEADS, SEQ / 64), 256>>>(gv, gvt);

    // 6) Causal flash attention; writes split A operand for out-proj
    attn_tc_kernel<<<dim3(SEQ / 64, BATCH * NHEADS), 256, attn_smem>>>(
        qhi, qmid, gk, gvt, ahi, amid);

    // 7) Output projection into d_out
    gemm_nt_tc_kernel<<<dim3(16, 32), 512, GEMM_SMEM_BYTES>>>(
        ahi, amid, gw, nullptr, nullptr,
        nullptr, nullptr, nullptr, nullptr, out, BT, DMODEL, DMODEL, 0);
}